// round 7
// baseline (speedup 1.0000x reference)
#include <cuda_runtime.h>
#include <cstdint>

#define BATCH 8
#define TLEN 64000
#define NFR 251
#define NB 513
#define NCH 32
#define NNODES 250
#define NODE_DIM 4116
#define SCC 20
#define EPSV 1e-5f

// ---------------- scratch (device globals; no allocation) ----------------
__device__ float g_s[BATCH * NB * NFR];
__device__ float2 g_tw[512];
__device__ float g_nodes[BATCH * NNODES * NODE_DIM];
__device__ float g_gh[BATCH * NNODES * 512];
__device__ float g_ssrc[BATCH * NNODES * 8];
__device__ float g_sdst[BATCH * NNODES * 8];
__device__ float g_g1[BATCH * NNODES * 512];
__device__ float g_h2g[BATCH * NNODES * 32];
__device__ float g_s2src[BATCH * NNODES];
__device__ float g_s2dst[BATCH * NNODES];

__device__ __forceinline__ uint32_t tf32r(float x) {
    uint32_t u;
    asm("cvt.rna.tf32.f32 %0, %1;" : "=r"(u) : "f"(x));
    return u;
}
__device__ __forceinline__ void mma_tf32(float* c,
                                         uint32_t a0, uint32_t a1, uint32_t a2, uint32_t a3,
                                         uint32_t b0, uint32_t b1) {
    asm volatile("mma.sync.aligned.m16n8k8.row.col.f32.tf32.tf32.f32 "
                 "{%0,%1,%2,%3},{%4,%5,%6,%7},{%8,%9},{%0,%1,%2,%3};"
                 : "+f"(c[0]), "+f"(c[1]), "+f"(c[2]), "+f"(c[3])
                 : "r"(a0), "r"(a1), "r"(a2), "r"(a3), "r"(b0), "r"(b1));
}

// ---------------- twiddle table init ----------------
__global__ void k_twinit() {
    int t = threadIdx.x;
    float ang = -6.283185307179586f * (float)t / 1024.f;
    float si, co;
    sincosf(ang, &si, &co);
    g_tw[t] = make_float2(co, si);
}

// ---------------- sinc conv (only first 1000 outputs needed) ----------------
__global__ void k_sinc(const float* __restrict__ x, const float* __restrict__ w) {
    __shared__ float sw[1024];
    __shared__ float sx[1536];
    int b = blockIdx.x / SCC, c = blockIdx.x % SCC;
    for (int i = threadIdx.x; i < 1024; i += 256) sw[i] = w[c * 1024 + i];
    for (int i = threadIdx.x; i < 1536; i += 256)
        sx[i] = (i < 1512) ? x[b * TLEN + i] : 0.f;
    __syncthreads();
    for (int t = threadIdx.x; t < NNODES; t += 256) {
        float acc = 0.f;
        for (int q = 0; q < 4; q++) {
            int p = 4 * t + q;
            int k0 = 512 - p; if (k0 < 0) k0 = 0;
            const float* xs = sx + p - 512;
            for (int k = k0; k < 1024; k++) acc = fmaf(sw[k], xs[k], acc);
        }
        g_nodes[(b * NNODES + t) * NODE_DIM + c] = acc * 0.25f;
    }
}

// ---------------- STFT: pair-packed 1024-pt FFT (2 real frames per FFT) -----
__device__ __forceinline__ int reflect_idx(int m) {
    if (m < 0) m = -m;
    else if (m >= TLEN) m = 2 * TLEN - 2 - m;
    return m;
}
__global__ void k_stft(const float* __restrict__ x) {
    __shared__ float re[1024], im[1024];
    __shared__ float2 tw[512];
    int b = blockIdx.x / 126, p = blockIdx.x % 126;
    int t = threadIdx.x;
    tw[t] = g_tw[t];
    int fr1 = 2 * p;
    int has2 = (p < 125);
    int base1 = fr1 * 256 - 512;
    for (int n = t; n < 1024; n += 512) {
        int m1 = reflect_idx(base1 + n);
        float v1 = x[b * TLEN + m1];
        float v2 = 0.f;
        if (has2) {
            int m2 = reflect_idx(base1 + 256 + n);
            v2 = x[b * TLEN + m2];
        }
        int r = (int)(__brev((unsigned)n) >> 22);
        re[r] = v1;
        im[r] = v2;
    }
    __syncthreads();
    int mult = 512;
#pragma unroll
    for (int len = 2; len <= 32; len <<= 1) {
        int half = len >> 1;
        int j = t & (half - 1);
        int pos = (t / half) * len + j;
        float2 wv = tw[j * mult];
        float co = wv.x, si = wv.y;
        float ur = re[pos], ui = im[pos];
        float vr = re[pos + half], vi = im[pos + half];
        float tr = vr * co - vi * si;
        float ti = vr * si + vi * co;
        re[pos] = ur + tr; im[pos] = ui + ti;
        re[pos + half] = ur - tr; im[pos + half] = ui - ti;
        mult >>= 1;
        __syncwarp();
    }
    __syncthreads();
#pragma unroll
    for (int len = 64; len <= 1024; len <<= 1) {
        int half = len >> 1;
        int j = t & (half - 1);
        int pos = (t / half) * len + j;
        float2 wv = tw[j * mult];
        float co = wv.x, si = wv.y;
        float ur = re[pos], ui = im[pos];
        float vr = re[pos + half], vi = im[pos + half];
        float tr = vr * co - vi * si;
        float ti = vr * si + vi * co;
        re[pos] = ur + tr; im[pos] = ui + ti;
        re[pos + half] = ur - tr; im[pos + half] = ui - ti;
        mult >>= 1;
        __syncthreads();
    }
    for (int k = t; k <= 512; k += 512) {
        int nk = (1024 - k) & 1023;
        float zr = re[k], zi = im[k];
        float yr = re[nk], yi = im[nk];
        float m1 = 0.5f * sqrtf((zr + yr) * (zr + yr) + (zi - yi) * (zi - yi));
        g_s[(b * NB + k) * NFR + fr1] = logf(m1 + 1e-9f);
        if (has2) {
            float m2 = 0.5f * sqrtf((zi + yi) * (zi + yi) + (yr - zr) * (yr - zr));
            g_s[(b * NB + k) * NFR + fr1 + 1] = logf(m2 + 1e-9f);
        }
    }
}

// ---------------- fused conv1 + tf32-MMA conv2 + 2x2 maxpool + scatter -------
// 512 threads = 16 warps; tile 8 y-rows x 32 x-cols; warp (row=w>>1, half=w&1)
// does M=16 positions x N=32 co, K=288.
#define H1_STRIDE 36
#define W2_STRIDE 36
__global__ void k_fused(const float* __restrict__ w1, const float* __restrict__ b1,
                        const float* __restrict__ g1v, const float* __restrict__ be1,
                        const float* __restrict__ w2, const float* __restrict__ b2,
                        const float* __restrict__ g2v, const float* __restrict__ be2) {
    extern __shared__ float smem[];
    uint32_t* h1t = (uint32_t*)smem;                 // [10][34][36] = 12240
    uint32_t* wt2 = (uint32_t*)(smem + 12240);       // [9][co=32][ci pad36] = 10368
    float* sst = smem + 12240 + 10368;               // [12][36] = 432
    float* w1s = sst + 432;                          // 288
    float* pm = smem;                                // reuse: [8][32][33] = 8448

    int x0 = blockIdx.x * 32, y0 = blockIdx.y * 8, b = blockIdx.z;
    int tid = threadIdx.x;

    for (int i = tid; i < 9216; i += 512) {
        int ci = i & 31; int rest = i >> 5;
        int co = rest & 31; int kyx = rest >> 5;
        wt2[(kyx * 32 + co) * W2_STRIDE + ci] = tf32r(w2[(co * 32 + ci) * 9 + kyx]);
    }
    for (int i = tid; i < 288; i += 512) w1s[i] = w1[i];
    for (int i = tid; i < 12 * 36; i += 512) {
        int cc = i % 36, rr = i / 36;
        int gy = y0 - 2 + rr, gx = x0 - 2 + cc;
        float v = 0.f;
        if (gy >= 0 && gy < NB && gx >= 0 && gx < NFR)
            v = g_s[(b * NB + gy) * NFR + gx];
        sst[i] = v;
    }
    __syncthreads();

    {
        int ci = tid & 31;
        float cb1 = b1[ci];
        float sc1 = g1v[ci] * rsqrtf(1.f + EPSV);
        float bb1 = be1[ci];
        const float* wp = w1s + ci * 9;
        for (int r = tid >> 5; r < 340; r += 16) {
            int cc = r % 34, rr = r / 34;
            int y = y0 - 1 + rr, xg = x0 - 1 + cc;
            float v = 0.f;
            if (y >= 0 && y < NB && xg >= 0 && xg < NFR) {
                float acc = cb1;
#pragma unroll
                for (int ky = 0; ky < 3; ky++)
#pragma unroll
                    for (int kx = 0; kx < 3; kx++)
                        acc = fmaf(wp[ky * 3 + kx], sst[(rr + ky) * 36 + (cc + kx)], acc);
                acc = acc * sc1 + bb1;
                v = acc > 0.f ? acc : 0.f;
            }
            h1t[(rr * 34 + cc) * H1_STRIDE + ci] = tf32r(v);
        }
    }
    __syncthreads();

    int warp = tid >> 5, lane = tid & 31;
    int gid = lane >> 2, tig = lane & 3;
    int yy = warp >> 1;          // output row 0..7
    int mh = warp & 1;           // x-half 0..1
    float c[4][4] = {};
    int abase = (yy * 34 + mh * 16 + gid) * H1_STRIDE + tig;
#pragma unroll
    for (int ky = 0; ky < 3; ky++) {
#pragma unroll
        for (int kx = 0; kx < 3; kx++) {
            int kyx = ky * 3 + kx;
            int aoff0 = abase + (ky * 34 + kx) * H1_STRIDE;
            int boff0 = (kyx * 32 + gid) * W2_STRIDE + tig;
#pragma unroll
            for (int kc = 0; kc < 4; kc++) {
                uint32_t a[4], bf[4][2];
                {
                    int ao = aoff0 + kc * 8;
                    a[0] = h1t[ao];
                    a[1] = h1t[ao + 8 * H1_STRIDE];
                    a[2] = h1t[ao + 4];
                    a[3] = h1t[ao + 8 * H1_STRIDE + 4];
                }
#pragma unroll
                for (int nt = 0; nt < 4; nt++) {
                    int bo = boff0 + nt * 8 * W2_STRIDE + kc * 8;
                    bf[nt][0] = wt2[bo];
                    bf[nt][1] = wt2[bo + 4];
                }
#pragma unroll
                for (int nt = 0; nt < 4; nt++)
                    mma_tf32(c[nt], a[0], a[1], a[2], a[3], bf[nt][0], bf[nt][1]);
            }
        }
    }
    __syncthreads();

    float rs = rsqrtf(1.f + EPSV);
#pragma unroll
    for (int nt = 0; nt < 4; nt++) {
        int co0 = nt * 8 + tig * 2;
        float cb0 = b2[co0], sc0 = g2v[co0] * rs, bb0 = be2[co0];
        float cb1v = b2[co0 + 1], sc1v = g2v[co0 + 1] * rs, bb1v = be2[co0 + 1];
        int xa = mh * 16 + gid;
        int xbp = xa + 8;
        float v0 = fmaxf((c[nt][0] + cb0) * sc0 + bb0, 0.f);
        float v1 = fmaxf((c[nt][1] + cb1v) * sc1v + bb1v, 0.f);
        float v2 = fmaxf((c[nt][2] + cb0) * sc0 + bb0, 0.f);
        float v3 = fmaxf((c[nt][3] + cb1v) * sc1v + bb1v, 0.f);
        pm[(yy * 32 + xa) * 33 + co0] = v0;
        pm[(yy * 32 + xa) * 33 + co0 + 1] = v1;
        pm[(yy * 32 + xbp) * 33 + co0] = v2;
        pm[(yy * 32 + xbp) * 33 + co0 + 1] = v3;
    }
    __syncthreads();

    int co = tid & 31, txp = tid >> 5;  // txp 0..15
    {
        int tp = (x0 >> 1) + txp;
        if (tp < 125) {
            float4 v;
#pragma unroll
            for (int fy = 0; fy < 4; fy++) {
                int yA = 2 * fy, yB = 2 * fy + 1;
                float m0 = fmaxf(pm[(yA * 32 + 2 * txp) * 33 + co],
                                 pm[(yA * 32 + 2 * txp + 1) * 33 + co]);
                float m1 = fmaxf(pm[(yB * 32 + 2 * txp) * 33 + co],
                                 pm[(yB * 32 + 2 * txp + 1) * 33 + co]);
                ((float*)&v)[fy] = fmaxf(m0, m1);
            }
            int t = 2 * tp + (co >> 4);
            long off = (long)(b * NNODES + t) * NODE_DIM + SCC + (co & 15) * 256 + (y0 >> 1);
            *(float4*)(g_nodes + off) = v;
        }
    }
}

// ---------------- gemm1: split-tf32 (3-term), 128x64, double-buffered --------
#define AP 20
#define BP 72
__global__ void k_gemm1_t(const float* __restrict__ Wg) {
    extern __shared__ uint32_t gsm[];
    uint32_t* Ah = gsm;                 // [2][128*20]
    uint32_t* Al = gsm + 2 * 2560;
    uint32_t* Bh = gsm + 4 * 2560;      // [2][16*72]
    uint32_t* Bl = gsm + 4 * 2560 + 2 * 1152;
    const int M = BATCH * NNODES, N = 512, K = NODE_DIM;
    const int KT = (K + 15) / 16;       // 258
    int bx = blockIdx.x, by = blockIdx.y;
    int tid = threadIdx.x;
    int warp = tid >> 5, lane = tid & 31;
    int gid = lane >> 2, tig = lane & 3;
    int wm = (warp >> 1) * 32, wn = (warp & 1) * 32;
    float c[2][4][4] = {};

#pragma unroll
    for (int j = 0; j < 8; j++) {
        int i = tid + j * 256;
        int m = i >> 4, kk = i & 15;
        int gm = by * 128 + m;
        float v = (gm < M) ? g_nodes[(long)gm * K + kk] : 0.f;
        uint32_t hi = tf32r(v);
        Ah[m * AP + kk] = hi;
        Al[m * AP + kk] = tf32r(v - __uint_as_float(hi));
    }
#pragma unroll
    for (int j = 0; j < 4; j++) {
        int i = tid + j * 256;
        int kk = i >> 6, n = i & 63;
        float v = Wg[(long)kk * N + bx * 64 + n];
        uint32_t hi = tf32r(v);
        Bh[kk * BP + n] = hi;
        Bl[kk * BP + n] = tf32r(v - __uint_as_float(hi));
    }
    __syncthreads();

    for (int kt = 0; kt < KT; kt++) {
        int buf = kt & 1;
        uint32_t* ah_ = Ah + buf * 2560;
        uint32_t* al_ = Al + buf * 2560;
        uint32_t* bh_ = Bh + buf * 1152;
        uint32_t* bl_ = Bl + buf * 1152;
        float ra[8], rb[4];
        if (kt + 1 < KT) {
            int k0n = (kt + 1) * 16;
#pragma unroll
            for (int j = 0; j < 8; j++) {
                int i = tid + j * 256;
                int m = i >> 4, kk = i & 15;
                int gm = by * 128 + m, gk = k0n + kk;
                ra[j] = (gm < M && gk < K) ? g_nodes[(long)gm * K + gk] : 0.f;
            }
#pragma unroll
            for (int j = 0; j < 4; j++) {
                int i = tid + j * 256;
                int kk = i >> 6, n = i & 63;
                int gk = k0n + kk;
                rb[j] = (gk < K) ? Wg[(long)gk * N + bx * 64 + n] : 0.f;
            }
        }
#pragma unroll
        for (int ks = 0; ks < 16; ks += 8) {
            uint32_t ah[2][4], al[2][4], bh[4][2], bl[4][2];
#pragma unroll
            for (int mi = 0; mi < 2; mi++) {
                int mb = wm + mi * 16;
                int i0 = (mb + gid) * AP + ks + tig;
                int i1 = (mb + gid + 8) * AP + ks + tig;
                ah[mi][0] = ah_[i0]; ah[mi][1] = ah_[i1];
                ah[mi][2] = ah_[i0 + 4]; ah[mi][3] = ah_[i1 + 4];
                al[mi][0] = al_[i0]; al[mi][1] = al_[i1];
                al[mi][2] = al_[i0 + 4]; al[mi][3] = al_[i1 + 4];
            }
#pragma unroll
            for (int ni = 0; ni < 4; ni++) {
                int nb = wn + ni * 8;
                bh[ni][0] = bh_[(ks + tig) * BP + nb + gid];
                bh[ni][1] = bh_[(ks + tig + 4) * BP + nb + gid];
                bl[ni][0] = bl_[(ks + tig) * BP + nb + gid];
                bl[ni][1] = bl_[(ks + tig + 4) * BP + nb + gid];
            }
#pragma unroll
            for (int mi = 0; mi < 2; mi++)
#pragma unroll
                for (int ni = 0; ni < 4; ni++) {
                    mma_tf32(c[mi][ni], ah[mi][0], ah[mi][1], ah[mi][2], ah[mi][3],
                             bl[ni][0], bl[ni][1]);
                    mma_tf32(c[mi][ni], al[mi][0], al[mi][1], al[mi][2], al[mi][3],
                             bh[ni][0], bh[ni][1]);
                    mma_tf32(c[mi][ni], ah[mi][0], ah[mi][1], ah[mi][2], ah[mi][3],
                             bh[ni][0], bh[ni][1]);
                }
        }
        if (kt + 1 < KT) {
            int nb2 = (kt + 1) & 1;
            uint32_t* ah2 = Ah + nb2 * 2560;
            uint32_t* al2 = Al + nb2 * 2560;
            uint32_t* bh2 = Bh + nb2 * 1152;
            uint32_t* bl2 = Bl + nb2 * 1152;
#pragma unroll
            for (int j = 0; j < 8; j++) {
                int i = tid + j * 256;
                int m = i >> 4, kk = i & 15;
                uint32_t hi = tf32r(ra[j]);
                ah2[m * AP + kk] = hi;
                al2[m * AP + kk] = tf32r(ra[j] - __uint_as_float(hi));
            }
#pragma unroll
            for (int j = 0; j < 4; j++) {
                int i = tid + j * 256;
                int kk = i >> 6, n = i & 63;
                uint32_t hi = tf32r(rb[j]);
                bh2[kk * BP + n] = hi;
                bl2[kk * BP + n] = tf32r(rb[j] - __uint_as_float(hi));
            }
        }
        __syncthreads();
    }
#pragma unroll
    for (int mi = 0; mi < 2; mi++) {
        int r0 = by * 128 + wm + mi * 16 + gid;
        int r1 = r0 + 8;
#pragma unroll
        for (int ni = 0; ni < 4; ni++) {
            int gcol = bx * 64 + wn + ni * 8 + tig * 2;
            if (r0 < M) {
                float2 v = {c[mi][ni][0], c[mi][ni][1]};
                *(float2*)(g_gh + (long)r0 * N + gcol) = v;
            }
            if (r1 < M) {
                float2 v = {c[mi][ni][2], c[mi][ni][3]};
                *(float2*)(g_gh + (long)r1 * N + gcol) = v;
            }
        }
    }
}

// ---------------- generic tiled SGEMM (64x64x16) body ------------------------
__device__ __forceinline__ void gemm_body(const float* __restrict__ A,
                                          const float* __restrict__ B,
                                          float* __restrict__ C,
                                          int M, int N, int K) {
    __shared__ float As[16][65];
    __shared__ float Bs[16][64];
    int bx = blockIdx.x, by = blockIdx.y;
    int tid = threadIdx.x;
    int tr = tid >> 4, tc = tid & 15;
    float acc[4][4] = {};
    for (int k0 = 0; k0 < K; k0 += 16) {
        for (int i = tid; i < 64 * 16; i += 256) {
            int m = i >> 4, kk = i & 15;
            int gm = by * 64 + m, gk = k0 + kk;
            As[kk][m] = (gm < M && gk < K) ? A[(long)gm * K + gk] : 0.f;
        }
        for (int i = tid; i < 16 * 64; i += 256) {
            int kk = i >> 6, n = i & 63;
            int gk = k0 + kk, gn = bx * 64 + n;
            Bs[kk][n] = (gk < K && gn < N) ? B[(long)gk * N + gn] : 0.f;
        }
        __syncthreads();
#pragma unroll
        for (int kk = 0; kk < 16; kk++) {
            float a[4], bv[4];
#pragma unroll
            for (int i = 0; i < 4; i++) a[i] = As[kk][tr * 4 + i];
#pragma unroll
            for (int jq = 0; jq < 4; jq++) bv[jq] = Bs[kk][tc * 4 + jq];
#pragma unroll
            for (int i = 0; i < 4; i++)
#pragma unroll
                for (int jq = 0; jq < 4; jq++)
                    acc[i][jq] = fmaf(a[i], bv[jq], acc[i][jq]);
        }
        __syncthreads();
    }
    for (int i = 0; i < 4; i++) {
        int gm = by * 64 + tr * 4 + i;
        if (gm >= M) continue;
        for (int jq = 0; jq < 4; jq++) {
            int gn = bx * 64 + tc * 4 + jq;
            if (gn < N) C[(long)gm * N + gn] = acc[i][jq];
        }
    }
}

// ---------------- gemm2 + fused GAT2 scores ----------------
__global__ void k_gemm2(const float* __restrict__ W,
                        const float* __restrict__ asrc, const float* __restrict__ adst) {
    gemm_body(g_g1, W, g_h2g, BATCH * NNODES, 32, 512);
    __syncthreads();
    int tid = threadIdx.x;
    if (tid < 64) {
        int r = blockIdx.y * 64 + tid;
        if (r < BATCH * NNODES) {
            const float* hp = g_h2g + (long)r * 32;
            float s1 = 0.f, s2 = 0.f;
#pragma unroll
            for (int f = 0; f < 32; f++) {
                float v = hp[f];
                s1 = fmaf(v, asrc[f], s1);
                s2 = fmaf(v, adst[f], s2);
            }
            g_s2src[r] = s1;
            g_s2dst[r] = s2;
        }
    }
}

// ---------------- GAT1 attention scores ----------------
__global__ void k_scores1(const float* __restrict__ asrc, const float* __restrict__ adst) {
    int idx = blockIdx.x * 256 + threadIdx.x;
    if (idx >= BATCH * NNODES * 8) return;
    int h = idx & 7;
    int bn = idx >> 3;
    const float* hp = g_gh + (long)bn * 512 + h * 64;
    float s1 = 0.f, s2 = 0.f;
    for (int f = 0; f < 64; f++) {
        float v = hp[f];
        s1 = fmaf(v, asrc[h * 64 + f], s1);
        s2 = fmaf(v, adst[h * 64 + f], s2);
    }
    g_ssrc[idx] = s1;
    g_sdst[idx] = s2;
}

// ---------------- GAT1 softmax-attention + aggregate (10 i per block) --------
__global__ void k_att1(const float* __restrict__ bias) {
    extern __shared__ float sm[];
    float* swj = sm;               // [10][250][8] = 20000
    float* ss = sm + 20000;        // 2000
    float* sums = sm + 22000;      // 80
    int b = blockIdx.x / 25, ig = blockIdx.x % 25;
    int i0 = ig * 10;
    int tid = threadIdx.x;
    for (int i = tid; i < 2000; i += 256) ss[i] = g_ssrc[b * 2000 + i];
    __syncthreads();
    int warp = tid >> 5, lane = tid & 31;
    for (int task = warp; task < 80; task += 8) {
        int ii = task >> 3, h = task & 7;
        float d = g_sdst[(b * NNODES + i0 + ii) * 8 + h];
        float mx = -1e30f;
        for (int j = lane; j < NNODES; j += 32) {
            float e = d + ss[j * 8 + h];
            e = e > 0.f ? e : 0.2f * e;
            mx = fmaxf(mx, e);
        }
#pragma unroll
        for (int o = 16; o; o >>= 1) mx = fmaxf(mx, __shfl_xor_sync(0xffffffffu, mx, o));
        float smv = 0.f;
        for (int j = lane; j < NNODES; j += 32) {
            float e = d + ss[j * 8 + h];
            e = e > 0.f ? e : 0.2f * e;
            float wv = expf(e - mx);
            swj[(ii * NNODES + j) * 8 + h] = wv;
            smv += wv;
        }
#pragma unroll
        for (int o = 16; o; o >>= 1) smv += __shfl_xor_sync(0xffffffffu, smv, o);
        if (!lane) sums[ii * 8 + h] = smv;
    }
    __syncthreads();
    float acc0[10], acc1[10];
#pragma unroll
    for (int ii = 0; ii < 10; ii++) { acc0[ii] = 0.f; acc1[ii] = 0.f; }
    const float* Hb = g_gh + (long)b * NNODES * 512;
    int f0 = tid, f1 = tid + 256;
    int h0 = f0 >> 6, h1 = f1 >> 6;
    for (int j = 0; j < NNODES; j++) {
        float v0 = Hb[j * 512 + f0];
        float v1 = Hb[j * 512 + f1];
#pragma unroll
        for (int ii = 0; ii < 10; ii++) {
            acc0[ii] = fmaf(swj[(ii * NNODES + j) * 8 + h0], v0, acc0[ii]);
            acc1[ii] = fmaf(swj[(ii * NNODES + j) * 8 + h1], v1, acc1[ii]);
        }
    }
    float bi0 = bias[f0], bi1 = bias[f1];
    for (int ii = 0; ii < 10; ii++) {
        int i = i0 + ii;
        float* op = g_g1 + (long)(b * NNODES + i) * 512;
        float o0 = acc0[ii] / sums[ii * 8 + h0] + bi0;
        float o1 = acc1[ii] / sums[ii * 8 + h1] + bi1;
        op[f0] = o0 > 0.f ? o0 : 0.f;
        op[f1] = o1 > 0.f ? o1 : 0.f;
    }
}

// ---------------- GAT2 attention + aggregate + mean-pool + FC head -----------
__global__ void k_att2(const float* __restrict__ bias,
                       const float* __restrict__ fc1w, const float* __restrict__ fc1b,
                       const float* __restrict__ bg, const float* __restrict__ bb2,
                       const float* __restrict__ fc2w, const float* __restrict__ fc2b,
                       float* __restrict__ out, int write_emb) {
    extern __shared__ float am[];
    float* sh = am;                // [250*32] = 8000
    float* ssr = am + 8000;        // 256
    float* wjs = am + 8256;        // [8][250] = 2000
    float* sout = am + 10256;      // [250*32] = 8000
    float* sz = am + 18256;        // 128
    int b = blockIdx.x;
    int tid = threadIdx.x, warp = tid >> 5, lane = tid & 31;
    for (int i = tid; i < NNODES * 32; i += 256) sh[i] = g_h2g[b * NNODES * 32 + i];
    for (int i = tid; i < NNODES; i += 256) ssr[i] = g_s2src[b * NNODES + i];
    __syncthreads();
    float bi = bias[lane];
    for (int i = warp; i < NNODES; i += 8) {
        float d = g_s2dst[b * NNODES + i];
        float mx = -1e30f;
        for (int j = lane; j < NNODES; j += 32) {
            float e = d + ssr[j];
            e = e > 0.f ? e : 0.2f * e;
            mx = fmaxf(mx, e);
        }
#pragma unroll
        for (int o = 16; o; o >>= 1) mx = fmaxf(mx, __shfl_xor_sync(0xffffffffu, mx, o));
        float sum = 0.f;
        for (int j = lane; j < NNODES; j += 32) {
            float e = d + ssr[j];
            e = e > 0.f ? e : 0.2f * e;
            float wv = expf(e - mx);
            wjs[warp * NNODES + j] = wv;
            sum += wv;
        }
#pragma unroll
        for (int o = 16; o; o >>= 1) sum += __shfl_xor_sync(0xffffffffu, sum, o);
        __syncwarp();
        float acc = 0.f;
        for (int j = 0; j < NNODES; j++) acc = fmaf(wjs[warp * NNODES + j], sh[j * 32 + lane], acc);
        sout[i * 32 + lane] = acc / sum + bi;
    }
    __syncthreads();
    if (tid < 32) {
        float s = 0.f;
        for (int i = 0; i < NNODES; i++) s += sout[i * 32 + tid];
        s *= (1.f / 250.f);
        ssr[tid] = s;
        if (write_emb) out[16 + b * 32 + tid] = s;
    }
    __syncthreads();
    if (tid < 128) {
        float z = fc1b[tid];
        for (int f = 0; f < 32; f++) z = fmaf(ssr[f], fc1w[f * 128 + tid], z);
        z = z * (bg[tid] * rsqrtf(1.f + EPSV)) + bb2[tid];
        sz[tid] = z > 0.f ? z : 0.f;
    }
    __syncthreads();
    if (tid < 2) {
        float o = fc2b[tid];
        for (int q = 0; q < 128; q++) o = fmaf(sz[q], fc2w[q * 2 + tid], o);
        out[b * 2 + tid] = o;
    }
}

extern "C" void kernel_launch(void* const* d_in, const int* in_sizes, int n_in,
                              void* d_out, int out_size) {
    const float* x = (const float*)d_in[0];
    const float* sinc_w = (const float*)d_in[1];
    const float* conv1_w = (const float*)d_in[2];
    const float* conv1_b = (const float*)d_in[3];
    const float* bn1_g = (const float*)d_in[4];
    const float* bn1_b = (const float*)d_in[5];
    const float* conv2_w = (const float*)d_in[6];
    const float* conv2_b = (const float*)d_in[7];
    const float* bn2_g = (const float*)d_in[8];
    const float* bn2_b = (const float*)d_in[9];
    const float* gat1_W = (const float*)d_in[10];
    const float* gat1_asrc = (const float*)d_in[11];
    const float* gat1_adst = (const float*)d_in[12];
    const float* gat1_bias = (const float*)d_in[13];
    const float* gat2_W = (const float*)d_in[14];
    const float* gat2_asrc = (const float*)d_in[15];
    const float* gat2_adst = (const float*)d_in[16];
    const float* gat2_bias = (const float*)d_in[17];
    const float* fc1_w = (const float*)d_in[18];
    const float* fc1_b = (const float*)d_in[19];
    const float* bnf_g = (const float*)d_in[20];
    const float* bnf_b = (const float*)d_in[21];
    const float* fc2_w = (const float*)d_in[22];
    const float* fc2_b = (const float*)d_in[23];

    const int FUSED_SMEM = 23328 * 4;
    const int GEMM1_SMEM = (4 * 2560 + 4 * 1152) * 4;   // 59392 B
    const int ATT2_SMEM = 18384 * 4;
    cudaFuncSetAttribute(k_fused, cudaFuncAttributeMaxDynamicSharedMemorySize, FUSED_SMEM);
    cudaFuncSetAttribute(k_gemm1_t, cudaFuncAttributeMaxDynamicSharedMemorySize, GEMM1_SMEM);
    cudaFuncSetAttribute(k_att1, cudaFuncAttributeMaxDynamicSharedMemorySize, 22080 * 4);
    cudaFuncSetAttribute(k_att2, cudaFuncAttributeMaxDynamicSharedMemorySize, ATT2_SMEM);

    k_twinit<<<1, 512>>>();
    k_sinc<<<BATCH * SCC, 256>>>(x, sinc_w);
    k_stft<<<BATCH * 126, 512>>>(x);

    dim3 gf(8, 64, BATCH);
    k_fused<<<gf, 512, FUSED_SMEM>>>(conv1_w, conv1_b, bn1_g, bn1_b,
                                     conv2_w, conv2_b, bn2_g, bn2_b);

    dim3 gg1(8, 16);
    k_gemm1_t<<<gg1, 256, GEMM1_SMEM>>>(gat1_W);
    k_scores1<<<(BATCH * NNODES * 8 + 255) / 256, 256>>>(gat1_asrc, gat1_adst);
    k_att1<<<BATCH * 25, 256, 22080 * 4>>>(gat1_bias);

    dim3 gg2(1, 32);
    k_gemm2<<<gg2, 256>>>(gat2_W, gat2_asrc, gat2_adst);

    int write_emb = (out_size >= 272) ? 1 : 0;
    k_att2<<<BATCH, 256, ATT2_SMEM>>>(gat2_bias, fc1_w, fc1_b, bnf_g, bnf_b,
                                      fc2_w, fc2_b, (float*)d_out, write_emb);
}

// round 8
// speedup vs baseline: 1.1122x; 1.1122x over previous
#include <cuda_runtime.h>
#include <cuda_bf16.h>
#include <cstdint>

#define BATCH 8
#define TLEN 64000
#define NFR 251
#define NB 513
#define NCH 32
#define NNODES 250
#define NODE_DIM 4116
#define SCC 20
#define EPSV 1e-5f

// ---------------- scratch (device globals; no allocation) ----------------
__device__ float g_s[BATCH * NB * NFR];
__device__ float2 g_tw[512];
__device__ float g_nodes[BATCH * NNODES * NODE_DIM];
__device__ float g_gh[BATCH * NNODES * 512];
__device__ float g_ssrc[BATCH * NNODES * 8];
__device__ float g_sdst[BATCH * NNODES * 8];
__device__ float g_g1[BATCH * NNODES * 512];
__device__ float g_h2g[BATCH * NNODES * 32];
__device__ float g_s2src[BATCH * NNODES];
__device__ float g_s2dst[BATCH * NNODES];

__device__ __forceinline__ uint32_t tf32r(float x) {
    uint32_t u;
    asm("cvt.rna.tf32.f32 %0, %1;" : "=r"(u) : "f"(x));
    return u;
}
__device__ __forceinline__ void mma_tf32(float* c,
                                         uint32_t a0, uint32_t a1, uint32_t a2, uint32_t a3,
                                         uint32_t b0, uint32_t b1) {
    asm volatile("mma.sync.aligned.m16n8k8.row.col.f32.tf32.tf32.f32 "
                 "{%0,%1,%2,%3},{%4,%5,%6,%7},{%8,%9},{%0,%1,%2,%3};"
                 : "+f"(c[0]), "+f"(c[1]), "+f"(c[2]), "+f"(c[3])
                 : "r"(a0), "r"(a1), "r"(a2), "r"(a3), "r"(b0), "r"(b1));
}
__device__ __forceinline__ void mma_bf16(float* c,
                                         uint32_t a0, uint32_t a1, uint32_t a2, uint32_t a3,
                                         uint32_t b0, uint32_t b1) {
    asm volatile("mma.sync.aligned.m16n8k16.row.col.f32.bf16.bf16.f32 "
                 "{%0,%1,%2,%3},{%4,%5,%6,%7},{%8,%9},{%0,%1,%2,%3};"
                 : "+f"(c[0]), "+f"(c[1]), "+f"(c[2]), "+f"(c[3])
                 : "r"(a0), "r"(a1), "r"(a2), "r"(a3), "r"(b0), "r"(b1));
}
// split two fp32 into packed bf16 hi + bf16 lo (x in low half, y in high half)
__device__ __forceinline__ void split2(float x, float y, uint32_t& hi, uint32_t& lo) {
    __nv_bfloat162 h = __floats2bfloat162_rn(x, y);
    float rx = x - __bfloat162float(h.x);
    float ry = y - __bfloat162float(h.y);
    __nv_bfloat162 l = __floats2bfloat162_rn(rx, ry);
    hi = *(uint32_t*)&h;
    lo = *(uint32_t*)&l;
}

// ---------------- twiddle table init ----------------
__global__ void k_twinit() {
    int t = threadIdx.x;
    float ang = -6.283185307179586f * (float)t / 1024.f;
    float si, co;
    sincosf(ang, &si, &co);
    g_tw[t] = make_float2(co, si);
}

// ---------------- sinc conv (only first 1000 outputs needed) ----------------
__global__ void k_sinc(const float* __restrict__ x, const float* __restrict__ w) {
    __shared__ float sw[1024];
    __shared__ float sx[1536];
    int b = blockIdx.x / SCC, c = blockIdx.x % SCC;
    for (int i = threadIdx.x; i < 1024; i += 256) sw[i] = w[c * 1024 + i];
    for (int i = threadIdx.x; i < 1536; i += 256)
        sx[i] = (i < 1512) ? x[b * TLEN + i] : 0.f;
    __syncthreads();
    for (int t = threadIdx.x; t < NNODES; t += 256) {
        float acc = 0.f;
        for (int q = 0; q < 4; q++) {
            int p = 4 * t + q;
            int k0 = 512 - p; if (k0 < 0) k0 = 0;
            const float* xs = sx + p - 512;
            for (int k = k0; k < 1024; k++) acc = fmaf(sw[k], xs[k], acc);
        }
        g_nodes[(b * NNODES + t) * NODE_DIM + c] = acc * 0.25f;
    }
}

// ---------------- STFT: pair-packed 1024-pt FFT (2 real frames per FFT) -----
__device__ __forceinline__ int reflect_idx(int m) {
    if (m < 0) m = -m;
    else if (m >= TLEN) m = 2 * TLEN - 2 - m;
    return m;
}
__global__ void k_stft(const float* __restrict__ x) {
    __shared__ float re[1024], im[1024];
    __shared__ float2 tw[512];
    int b = blockIdx.x / 126, p = blockIdx.x % 126;
    int t = threadIdx.x;
    tw[t] = g_tw[t];
    int fr1 = 2 * p;
    int has2 = (p < 125);
    int base1 = fr1 * 256 - 512;
    for (int n = t; n < 1024; n += 512) {
        int m1 = reflect_idx(base1 + n);
        float v1 = x[b * TLEN + m1];
        float v2 = 0.f;
        if (has2) {
            int m2 = reflect_idx(base1 + 256 + n);
            v2 = x[b * TLEN + m2];
        }
        int r = (int)(__brev((unsigned)n) >> 22);
        re[r] = v1;
        im[r] = v2;
    }
    __syncthreads();
    int mult = 512;
    for (int len = 2; len <= 1024; len <<= 1) {
        int half = len >> 1;
        int j = t & (half - 1);
        int pos = (t / half) * len + j;
        float2 wv = tw[j * mult];
        float co = wv.x, si = wv.y;
        float ur = re[pos], ui = im[pos];
        float vr = re[pos + half], vi = im[pos + half];
        float tr = vr * co - vi * si;
        float ti = vr * si + vi * co;
        re[pos] = ur + tr; im[pos] = ui + ti;
        re[pos + half] = ur - tr; im[pos + half] = ui - ti;
        mult >>= 1;
        __syncthreads();
    }
    for (int k = t; k <= 512; k += 512) {
        int nk = (1024 - k) & 1023;
        float zr = re[k], zi = im[k];
        float yr = re[nk], yi = im[nk];
        float m1 = 0.5f * sqrtf((zr + yr) * (zr + yr) + (zi - yi) * (zi - yi));
        g_s[(b * NB + k) * NFR + fr1] = logf(m1 + 1e-9f);
        if (has2) {
            float m2 = 0.5f * sqrtf((zi + yi) * (zi + yi) + (yr - zr) * (yr - zr));
            g_s[(b * NB + k) * NFR + fr1 + 1] = logf(m2 + 1e-9f);
        }
    }
}

// ---------------- fused conv1 + tf32-MMA conv2 + 2x2 maxpool + scatter -------
// 256 threads = 8 warps; warp yy does one output row: M=32, N=32, K=288
#define H1_STRIDE 36
#define W2_STRIDE 36
__global__ void k_fused(const float* __restrict__ w1, const float* __restrict__ b1,
                        const float* __restrict__ g1v, const float* __restrict__ be1,
                        const float* __restrict__ w2, const float* __restrict__ b2,
                        const float* __restrict__ g2v, const float* __restrict__ be2) {
    extern __shared__ float smem[];
    uint32_t* h1t = (uint32_t*)smem;                 // [10][34][36] = 12240
    uint32_t* wt2 = (uint32_t*)(smem + 12240);       // [9][co=32][ci pad36] = 10368
    float* sst = smem + 12240 + 10368;               // [12][36] = 432
    float* w1s = sst + 432;                          // 288
    float* pm = smem;                                // reuse: [8][32][33] = 8448

    int x0 = blockIdx.x * 32, y0 = blockIdx.y * 8, b = blockIdx.z;
    int tid = threadIdx.x;

    for (int i = tid; i < 9216; i += 256) {
        int ci = i & 31; int rest = i >> 5;
        int co = rest & 31; int kyx = rest >> 5;
        wt2[(kyx * 32 + co) * W2_STRIDE + ci] = tf32r(w2[(co * 32 + ci) * 9 + kyx]);
    }
    for (int i = tid; i < 288; i += 256) w1s[i] = w1[i];
    for (int i = tid; i < 12 * 36; i += 256) {
        int cc = i % 36, rr = i / 36;
        int gy = y0 - 2 + rr, gx = x0 - 2 + cc;
        float v = 0.f;
        if (gy >= 0 && gy < NB && gx >= 0 && gx < NFR)
            v = g_s[(b * NB + gy) * NFR + gx];
        sst[i] = v;
    }
    __syncthreads();

    {
        int ci = tid & 31;
        float cb1 = b1[ci];
        float sc1 = g1v[ci] * rsqrtf(1.f + EPSV);
        float bb1 = be1[ci];
        const float* wp = w1s + ci * 9;
        for (int r = tid >> 5; r < 340; r += 8) {
            int cc = r % 34, rr = r / 34;
            int y = y0 - 1 + rr, xg = x0 - 1 + cc;
            float v = 0.f;
            if (y >= 0 && y < NB && xg >= 0 && xg < NFR) {
                float acc = cb1;
#pragma unroll
                for (int ky = 0; ky < 3; ky++)
#pragma unroll
                    for (int kx = 0; kx < 3; kx++)
                        acc = fmaf(wp[ky * 3 + kx], sst[(rr + ky) * 36 + (cc + kx)], acc);
                acc = acc * sc1 + bb1;
                v = acc > 0.f ? acc : 0.f;
            }
            h1t[(rr * 34 + cc) * H1_STRIDE + ci] = tf32r(v);
        }
    }
    __syncthreads();

    int warp = tid >> 5, lane = tid & 31;
    int gid = lane >> 2, tig = lane & 3;
    int yy = warp;
    float c[2][4][4] = {};
    int abase = (yy * 34 + gid) * H1_STRIDE + tig;
#pragma unroll
    for (int ky = 0; ky < 3; ky++) {
#pragma unroll
        for (int kx = 0; kx < 3; kx++) {
            int kyx = ky * 3 + kx;
            int aoff0 = abase + (ky * 34 + kx) * H1_STRIDE;
            int boff0 = (kyx * 32 + gid) * W2_STRIDE + tig;
#pragma unroll
            for (int kc = 0; kc < 4; kc++) {
                uint32_t a[2][4], bf[4][2];
#pragma unroll
                for (int mt = 0; mt < 2; mt++) {
                    int ao = aoff0 + mt * 16 * H1_STRIDE + kc * 8;
                    a[mt][0] = h1t[ao];
                    a[mt][1] = h1t[ao + 8 * H1_STRIDE];
                    a[mt][2] = h1t[ao + 4];
                    a[mt][3] = h1t[ao + 8 * H1_STRIDE + 4];
                }
#pragma unroll
                for (int nt = 0; nt < 4; nt++) {
                    int bo = boff0 + nt * 8 * W2_STRIDE + kc * 8;
                    bf[nt][0] = wt2[bo];
                    bf[nt][1] = wt2[bo + 4];
                }
#pragma unroll
                for (int mt = 0; mt < 2; mt++)
#pragma unroll
                    for (int nt = 0; nt < 4; nt++)
                        mma_tf32(c[mt][nt], a[mt][0], a[mt][1], a[mt][2], a[mt][3],
                                 bf[nt][0], bf[nt][1]);
            }
        }
    }
    __syncthreads();

    float rs = rsqrtf(1.f + EPSV);
#pragma unroll
    for (int nt = 0; nt < 4; nt++) {
        int co0 = nt * 8 + tig * 2;
        float cb0 = b2[co0], sc0 = g2v[co0] * rs, bb0 = be2[co0];
        float cb1v = b2[co0 + 1], sc1v = g2v[co0 + 1] * rs, bb1v = be2[co0 + 1];
#pragma unroll
        for (int mt = 0; mt < 2; mt++) {
            int xa = mt * 16 + gid;
            int xbp = xa + 8;
            float v0 = fmaxf((c[mt][nt][0] + cb0) * sc0 + bb0, 0.f);
            float v1 = fmaxf((c[mt][nt][1] + cb1v) * sc1v + bb1v, 0.f);
            float v2 = fmaxf((c[mt][nt][2] + cb0) * sc0 + bb0, 0.f);
            float v3 = fmaxf((c[mt][nt][3] + cb1v) * sc1v + bb1v, 0.f);
            pm[(yy * 32 + xa) * 33 + co0] = v0;
            pm[(yy * 32 + xa) * 33 + co0 + 1] = v1;
            pm[(yy * 32 + xbp) * 33 + co0] = v2;
            pm[(yy * 32 + xbp) * 33 + co0 + 1] = v3;
        }
    }
    __syncthreads();

    int co = tid & 31, txh = tid >> 5;
#pragma unroll
    for (int t2 = 0; t2 < 2; t2++) {
        int txp = txh * 2 + t2;
        int tp = (x0 >> 1) + txp;
        if (tp < 125) {
            float4 v;
#pragma unroll
            for (int fy = 0; fy < 4; fy++) {
                int yA = 2 * fy, yB = 2 * fy + 1;
                float m0 = fmaxf(pm[(yA * 32 + 2 * txp) * 33 + co],
                                 pm[(yA * 32 + 2 * txp + 1) * 33 + co]);
                float m1 = fmaxf(pm[(yB * 32 + 2 * txp) * 33 + co],
                                 pm[(yB * 32 + 2 * txp + 1) * 33 + co]);
                ((float*)&v)[fy] = fmaxf(m0, m1);
            }
            int t = 2 * tp + (co >> 4);
            long off = (long)(b * NNODES + t) * NODE_DIM + SCC + (co & 15) * 256 + (y0 >> 1);
            *(float4*)(g_nodes + off) = v;
        }
    }
}

// ---------------- gemm1: 3-term bf16 split (Ootomo), 128x64, double-buffered -
// C = Ah*Bh + Ah*Bl + Al*Bh with bf16 m16n8k16; packed k-pairs in smem.
#define APB 12     // A pair-stride (conflict-free fragment banks)
#define BPB 72     // B pair row stride
#define ASZ 1536   // 128*12 words per split per buffer
#define BSZ 576    // 8*72
__global__ void k_gemm1_t(const float* __restrict__ Wg) {
    extern __shared__ uint32_t gsm[];
    uint32_t* AhB = gsm;                         // [2][ASZ]
    uint32_t* AlB = gsm + 2 * ASZ;
    uint32_t* BhB = gsm + 4 * ASZ;               // [2][BSZ]
    uint32_t* BlB = gsm + 4 * ASZ + 2 * BSZ;
    const int M = BATCH * NNODES, N = 512, K = NODE_DIM;
    const int KT = (K + 15) / 16;                // 258
    int bx = blockIdx.x, by = blockIdx.y;
    int tid = threadIdx.x;
    int warp = tid >> 5, lane = tid & 31;
    int gid = lane >> 2, tig = lane & 3;
    int wm = (warp >> 1) * 32, wn = (warp & 1) * 32;
    float c[2][4][4] = {};

    // stage tile 0 into buffer 0
#pragma unroll
    for (int j = 0; j < 4; j++) {
        int i = tid + j * 256;
        int m = i >> 3, kp = i & 7;
        int gm = by * 128 + m;
        float2 v = make_float2(0.f, 0.f);
        if (gm < M) v = *(const float2*)(g_nodes + (long)gm * K + 2 * kp);
        uint32_t hi, lo;
        split2(v.x, v.y, hi, lo);
        AhB[m * APB + kp] = hi;
        AlB[m * APB + kp] = lo;
    }
#pragma unroll
    for (int j = 0; j < 2; j++) {
        int i = tid + j * 256;
        int kp = i >> 6, n = i & 63;
        float v0 = Wg[(long)(2 * kp) * N + bx * 64 + n];
        float v1 = Wg[(long)(2 * kp + 1) * N + bx * 64 + n];
        uint32_t hi, lo;
        split2(v0, v1, hi, lo);
        BhB[kp * BPB + n] = hi;
        BlB[kp * BPB + n] = lo;
    }
    __syncthreads();

    for (int kt = 0; kt < KT; kt++) {
        int buf = kt & 1;
        uint32_t* ah_ = AhB + buf * ASZ;
        uint32_t* al_ = AlB + buf * ASZ;
        uint32_t* bh_ = BhB + buf * BSZ;
        uint32_t* bl_ = BlB + buf * BSZ;
        // prefetch next tile into registers
        float2 ra[4];
        float rb0[2], rb1[2];
        if (kt + 1 < KT) {
            int k0n = (kt + 1) * 16;
#pragma unroll
            for (int j = 0; j < 4; j++) {
                int i = tid + j * 256;
                int m = i >> 3, kp = i & 7;
                int gm = by * 128 + m, gk = k0n + 2 * kp;
                ra[j] = make_float2(0.f, 0.f);
                if (gm < M && gk < K)
                    ra[j] = *(const float2*)(g_nodes + (long)gm * K + gk);
            }
#pragma unroll
            for (int j = 0; j < 2; j++) {
                int i = tid + j * 256;
                int kp = i >> 6, n = i & 63;
                int gk = k0n + 2 * kp;
                rb0[j] = 0.f; rb1[j] = 0.f;
                if (gk < K) {
                    rb0[j] = Wg[(long)gk * N + bx * 64 + n];
                    rb1[j] = Wg[(long)(gk + 1) * N + bx * 64 + n];
                }
            }
        }
        // mma on current buffer (one K=16 step per tile)
        {
            uint32_t ah[2][4], al[2][4], bh[4][2], bl[4][2];
#pragma unroll
            for (int mi = 0; mi < 2; mi++) {
                int b0 = (wm + mi * 16 + gid) * APB;
                int b1 = (wm + mi * 16 + gid + 8) * APB;
                ah[mi][0] = ah_[b0 + tig]; ah[mi][1] = ah_[b1 + tig];
                ah[mi][2] = ah_[b0 + tig + 4]; ah[mi][3] = ah_[b1 + tig + 4];
                al[mi][0] = al_[b0 + tig]; al[mi][1] = al_[b1 + tig];
                al[mi][2] = al_[b0 + tig + 4]; al[mi][3] = al_[b1 + tig + 4];
            }
#pragma unroll
            for (int ni = 0; ni < 4; ni++) {
                int nb = wn + ni * 8 + gid;
                bh[ni][0] = bh_[tig * BPB + nb];
                bh[ni][1] = bh_[(tig + 4) * BPB + nb];
                bl[ni][0] = bl_[tig * BPB + nb];
                bl[ni][1] = bl_[(tig + 4) * BPB + nb];
            }
#pragma unroll
            for (int mi = 0; mi < 2; mi++)
#pragma unroll
                for (int ni = 0; ni < 4; ni++) {
                    mma_bf16(c[mi][ni], ah[mi][0], ah[mi][1], ah[mi][2], ah[mi][3],
                             bl[ni][0], bl[ni][1]);
                    mma_bf16(c[mi][ni], al[mi][0], al[mi][1], al[mi][2], al[mi][3],
                             bh[ni][0], bh[ni][1]);
                    mma_bf16(c[mi][ni], ah[mi][0], ah[mi][1], ah[mi][2], ah[mi][3],
                             bh[ni][0], bh[ni][1]);
                }
        }
        // store prefetched tile into other buffer
        if (kt + 1 < KT) {
            int nb2 = (kt + 1) & 1;
            uint32_t* ah2 = AhB + nb2 * ASZ;
            uint32_t* al2 = AlB + nb2 * ASZ;
            uint32_t* bh2 = BhB + nb2 * BSZ;
            uint32_t* bl2 = BlB + nb2 * BSZ;
#pragma unroll
            for (int j = 0; j < 4; j++) {
                int i = tid + j * 256;
                int m = i >> 3, kp = i & 7;
                uint32_t hi, lo;
                split2(ra[j].x, ra[j].y, hi, lo);
                ah2[m * APB + kp] = hi;
                al2[m * APB + kp] = lo;
            }
#pragma unroll
            for (int j = 0; j < 2; j++) {
                int i = tid + j * 256;
                int kp = i >> 6, n = i & 63;
                uint32_t hi, lo;
                split2(rb0[j], rb1[j], hi, lo);
                bh2[kp * BPB + n] = hi;
                bl2[kp * BPB + n] = lo;
            }
        }
        __syncthreads();
    }
#pragma unroll
    for (int mi = 0; mi < 2; mi++) {
        int r0 = by * 128 + wm + mi * 16 + gid;
        int r1 = r0 + 8;
#pragma unroll
        for (int ni = 0; ni < 4; ni++) {
            int gcol = bx * 64 + wn + ni * 8 + tig * 2;
            if (r0 < M) {
                float2 v = {c[mi][ni][0], c[mi][ni][1]};
                *(float2*)(g_gh + (long)r0 * N + gcol) = v;
            }
            if (r1 < M) {
                float2 v = {c[mi][ni][2], c[mi][ni][3]};
                *(float2*)(g_gh + (long)r1 * N + gcol) = v;
            }
        }
    }
}

// ---------------- generic tiled SGEMM (64x64x16) body ------------------------
__device__ __forceinline__ void gemm_body(const float* __restrict__ A,
                                          const float* __restrict__ B,
                                          float* __restrict__ C,
                                          int M, int N, int K) {
    __shared__ float As[16][65];
    __shared__ float Bs[16][64];
    int bx = blockIdx.x, by = blockIdx.y;
    int tid = threadIdx.x;
    int tr = tid >> 4, tc = tid & 15;
    float acc[4][4] = {};
    for (int k0 = 0; k0 < K; k0 += 16) {
        for (int i = tid; i < 64 * 16; i += 256) {
            int m = i >> 4, kk = i & 15;
            int gm = by * 64 + m, gk = k0 + kk;
            As[kk][m] = (gm < M && gk < K) ? A[(long)gm * K + gk] : 0.f;
        }
        for (int i = tid; i < 16 * 64; i += 256) {
            int kk = i >> 6, n = i & 63;
            int gk = k0 + kk, gn = bx * 64 + n;
            Bs[kk][n] = (gk < K && gn < N) ? B[(long)gk * N + gn] : 0.f;
        }
        __syncthreads();
#pragma unroll
        for (int kk = 0; kk < 16; kk++) {
            float a[4], bv[4];
#pragma unroll
            for (int i = 0; i < 4; i++) a[i] = As[kk][tr * 4 + i];
#pragma unroll
            for (int jq = 0; jq < 4; jq++) bv[jq] = Bs[kk][tc * 4 + jq];
#pragma unroll
            for (int i = 0; i < 4; i++)
#pragma unroll
                for (int jq = 0; jq < 4; jq++)
                    acc[i][jq] = fmaf(a[i], bv[jq], acc[i][jq]);
        }
        __syncthreads();
    }
    for (int i = 0; i < 4; i++) {
        int gm = by * 64 + tr * 4 + i;
        if (gm >= M) continue;
        for (int jq = 0; jq < 4; jq++) {
            int gn = bx * 64 + tc * 4 + jq;
            if (gn < N) C[(long)gm * N + gn] = acc[i][jq];
        }
    }
}

// ---------------- gemm2 + fused GAT2 scores ----------------
__global__ void k_gemm2(const float* __restrict__ W,
                        const float* __restrict__ asrc, const float* __restrict__ adst) {
    gemm_body(g_g1, W, g_h2g, BATCH * NNODES, 32, 512);
    __syncthreads();
    int tid = threadIdx.x;
    if (tid < 64) {
        int r = blockIdx.y * 64 + tid;
        if (r < BATCH * NNODES) {
            const float* hp = g_h2g + (long)r * 32;
            float s1 = 0.f, s2 = 0.f;
#pragma unroll
            for (int f = 0; f < 32; f++) {
                float v = hp[f];
                s1 = fmaf(v, asrc[f], s1);
                s2 = fmaf(v, adst[f], s2);
            }
            g_s2src[r] = s1;
            g_s2dst[r] = s2;
        }
    }
}

// ---------------- GAT1 attention scores ----------------
__global__ void k_scores1(const float* __restrict__ asrc, const float* __restrict__ adst) {
    int idx = blockIdx.x * 256 + threadIdx.x;
    if (idx >= BATCH * NNODES * 8) return;
    int h = idx & 7;
    int bn = idx >> 3;
    const float* hp = g_gh + (long)bn * 512 + h * 64;
    float s1 = 0.f, s2 = 0.f;
    for (int f = 0; f < 64; f++) {
        float v = hp[f];
        s1 = fmaf(v, asrc[h * 64 + f], s1);
        s2 = fmaf(v, adst[h * 64 + f], s2);
    }
    g_ssrc[idx] = s1;
    g_sdst[idx] = s2;
}

// ---------------- GAT1 softmax-attention + aggregate (10 i per block) --------
__global__ void k_att1(const float* __restrict__ bias) {
    extern __shared__ float sm[];
    float* swj = sm;               // [10][250][8] = 20000
    float* ss = sm + 20000;        // 2000
    float* sums = sm + 22000;      // 80
    int b = blockIdx.x / 25, ig = blockIdx.x % 25;
    int i0 = ig * 10;
    int tid = threadIdx.x;
    for (int i = tid; i < 2000; i += 256) ss[i] = g_ssrc[b * 2000 + i];
    __syncthreads();
    int warp = tid >> 5, lane = tid & 31;
    for (int task = warp; task < 80; task += 8) {
        int ii = task >> 3, h = task & 7;
        float d = g_sdst[(b * NNODES + i0 + ii) * 8 + h];
        float mx = -1e30f;
        for (int j = lane; j < NNODES; j += 32) {
            float e = d + ss[j * 8 + h];
            e = e > 0.f ? e : 0.2f * e;
            mx = fmaxf(mx, e);
        }
#pragma unroll
        for (int o = 16; o; o >>= 1) mx = fmaxf(mx, __shfl_xor_sync(0xffffffffu, mx, o));
        float smv = 0.f;
        for (int j = lane; j < NNODES; j += 32) {
            float e = d + ss[j * 8 + h];
            e = e > 0.f ? e : 0.2f * e;
            float wv = expf(e - mx);
            swj[(ii * NNODES + j) * 8 + h] = wv;
            smv += wv;
        }
#pragma unroll
        for (int o = 16; o; o >>= 1) smv += __shfl_xor_sync(0xffffffffu, smv, o);
        if (!lane) sums[ii * 8 + h] = smv;
    }
    __syncthreads();
    float acc0[10], acc1[10];
#pragma unroll
    for (int ii = 0; ii < 10; ii++) { acc0[ii] = 0.f; acc1[ii] = 0.f; }
    const float* Hb = g_gh + (long)b * NNODES * 512;
    int f0 = tid, f1 = tid + 256;
    int h0 = f0 >> 6, h1 = f1 >> 6;
    for (int j = 0; j < NNODES; j++) {
        float v0 = Hb[j * 512 + f0];
        float v1 = Hb[j * 512 + f1];
#pragma unroll
        for (int ii = 0; ii < 10; ii++) {
            acc0[ii] = fmaf(swj[(ii * NNODES + j) * 8 + h0], v0, acc0[ii]);
            acc1[ii] = fmaf(swj[(ii * NNODES + j) * 8 + h1], v1, acc1[ii]);
        }
    }
    float bi0 = bias[f0], bi1 = bias[f1];
    for (int ii = 0; ii < 10; ii++) {
        int i = i0 + ii;
        float* op = g_g1 + (long)(b * NNODES + i) * 512;
        float o0 = acc0[ii] / sums[ii * 8 + h0] + bi0;
        float o1 = acc1[ii] / sums[ii * 8 + h1] + bi1;
        op[f0] = o0 > 0.f ? o0 : 0.f;
        op[f1] = o1 > 0.f ? o1 : 0.f;
    }
}

// ---------------- GAT2 attention + aggregate + mean-pool + FC head -----------
__global__ void k_att2(const float* __restrict__ bias,
                       const float* __restrict__ fc1w, const float* __restrict__ fc1b,
                       const float* __restrict__ bg, const float* __restrict__ bb2,
                       const float* __restrict__ fc2w, const float* __restrict__ fc2b,
                       float* __restrict__ out, int write_emb) {
    extern __shared__ float am[];
    float* sh = am;                // [250*32] = 8000
    float* ssr = am + 8000;        // 256
    float* wjs = am + 8256;        // [8][250] = 2000
    float* sout = am + 10256;      // [250*32] = 8000
    float* sz = am + 18256;        // 128
    int b = blockIdx.x;
    int tid = threadIdx.x, warp = tid >> 5, lane = tid & 31;
    for (int i = tid; i < NNODES * 32; i += 256) sh[i] = g_h2g[b * NNODES * 32 + i];
    for (int i = tid; i < NNODES; i += 256) ssr[i] = g_s2src[b * NNODES + i];
    __syncthreads();
    float bi = bias[lane];
    for (int i = warp; i < NNODES; i += 8) {
        float d = g_s2dst[b * NNODES + i];
        float mx = -1e30f;
        for (int j = lane; j < NNODES; j += 32) {
            float e = d + ssr[j];
            e = e > 0.f ? e : 0.2f * e;
            mx = fmaxf(mx, e);
        }
#pragma unroll
        for (int o = 16; o; o >>= 1) mx = fmaxf(mx, __shfl_xor_sync(0xffffffffu, mx, o));
        float sum = 0.f;
        for (int j = lane; j < NNODES; j += 32) {
            float e = d + ssr[j];
            e = e > 0.f ? e : 0.2f * e;
            float wv = expf(e - mx);
            wjs[warp * NNODES + j] = wv;
            sum += wv;
        }
#pragma unroll
        for (int o = 16; o; o >>= 1) sum += __shfl_xor_sync(0xffffffffu, sum, o);
        __syncwarp();
        float acc = 0.f;
        for (int j = 0; j < NNODES; j++) acc = fmaf(wjs[warp * NNODES + j], sh[j * 32 + lane], acc);
        sout[i * 32 + lane] = acc / sum + bi;
    }
    __syncthreads();
    if (tid < 32) {
        float s = 0.f;
        for (int i = 0; i < NNODES; i++) s += sout[i * 32 + tid];
        s *= (1.f / 250.f);
        ssr[tid] = s;
        if (write_emb) out[16 + b * 32 + tid] = s;
    }
    __syncthreads();
    if (tid < 128) {
        float z = fc1b[tid];
        for (int f = 0; f < 32; f++) z = fmaf(ssr[f], fc1w[f * 128 + tid], z);
        z = z * (bg[tid] * rsqrtf(1.f + EPSV)) + bb2[tid];
        sz[tid] = z > 0.f ? z : 0.f;
    }
    __syncthreads();
    if (tid < 2) {
        float o = fc2b[tid];
        for (int q = 0; q < 128; q++) o = fmaf(sz[q], fc2w[q * 2 + tid], o);
        out[b * 2 + tid] = o;
    }
}

extern "C" void kernel_launch(void* const* d_in, const int* in_sizes, int n_in,
                              void* d_out, int out_size) {
    const float* x = (const float*)d_in[0];
    const float* sinc_w = (const float*)d_in[1];
    const float* conv1_w = (const float*)d_in[2];
    const float* conv1_b = (const float*)d_in[3];
    const float* bn1_g = (const float*)d_in[4];
    const float* bn1_b = (const float*)d_in[5];
    const float* conv2_w = (const float*)d_in[6];
    const float* conv2_b = (const float*)d_in[7];
    const float* bn2_g = (const float*)d_in[8];
    const float* bn2_b = (const float*)d_in[9];
    const float* gat1_W = (const float*)d_in[10];
    const float* gat1_asrc = (const float*)d_in[11];
    const float* gat1_adst = (const float*)d_in[12];
    const float* gat1_bias = (const float*)d_in[13];
    const float* gat2_W = (const float*)d_in[14];
    const float* gat2_asrc = (const float*)d_in[15];
    const float* gat2_adst = (const float*)d_in[16];
    const float* gat2_bias = (const float*)d_in[17];
    const float* fc1_w = (const float*)d_in[18];
    const float* fc1_b = (const float*)d_in[19];
    const float* bnf_g = (const float*)d_in[20];
    const float* bnf_b = (const float*)d_in[21];
    const float* fc2_w = (const float*)d_in[22];
    const float* fc2_b = (const float*)d_in[23];

    const int FUSED_SMEM = 23328 * 4;
    const int GEMM1_SMEM = (4 * ASZ + 4 * BSZ) * 4;   // 33792 B
    const int ATT2_SMEM = 18384 * 4;
    cudaFuncSetAttribute(k_fused, cudaFuncAttributeMaxDynamicSharedMemorySize, FUSED_SMEM);
    cudaFuncSetAttribute(k_gemm1_t, cudaFuncAttributeMaxDynamicSharedMemorySize, GEMM1_SMEM);
    cudaFuncSetAttribute(k_att1, cudaFuncAttributeMaxDynamicSharedMemorySize, 22080 * 4);
    cudaFuncSetAttribute(k_att2, cudaFuncAttributeMaxDynamicSharedMemorySize, ATT2_SMEM);

    k_twinit<<<1, 512>>>();
    k_sinc<<<BATCH * SCC, 256>>>(x, sinc_w);
    k_stft<<<BATCH * 126, 512>>>(x);

    dim3 gf(8, 64, BATCH);
    k_fused<<<gf, 256, FUSED_SMEM>>>(conv1_w, conv1_b, bn1_g, bn1_b,
                                     conv2_w, conv2_b, bn2_g, bn2_b);

    dim3 gg1(8, 16);
    k_gemm1_t<<<gg1, 256, GEMM1_SMEM>>>(gat1_W);
    k_scores1<<<(BATCH * NNODES * 8 + 255) / 256, 256>>>(gat1_asrc, gat1_adst);
    k_att1<<<BATCH * 25, 256, 22080 * 4>>>(gat1_bias);

    dim3 gg2(1, 32);
    k_gemm2<<<gg2, 256>>>(gat2_W, gat2_asrc, gat2_adst);

    int write_emb = (out_size >= 272) ? 1 : 0;
    k_att2<<<BATCH, 256, ATT2_SMEM>>>(gat2_bias, fc1_w, fc1_b, bnf_g, bnf_b,
                                      fc2_w, fc2_b, (float*)d_out, write_emb);
}

// round 10
// speedup vs baseline: 1.1218x; 1.0087x over previous
#include <cuda_runtime.h>
#include <cuda_bf16.h>
#include <cstdint>

#define BATCH 8
#define TLEN 64000
#define NFR 251
#define NB 513
#define NCH 32
#define NNODES 250
#define NODE_DIM 4116
#define SCC 20
#define EPSV 1e-5f

// ---------------- scratch (device globals; no allocation) ----------------
__device__ float g_s[BATCH * NB * NFR];
__device__ float2 g_tw[512];
__device__ float g_nodes[BATCH * NNODES * NODE_DIM];
__device__ float g_gh[BATCH * NNODES * 512];
__device__ float g_ssrc[BATCH * NNODES * 8];
__device__ float g_sdst[BATCH * NNODES * 8];
__device__ float g_g1[BATCH * NNODES * 512];
__device__ float g_h2g[BATCH * NNODES * 32];
__device__ float g_s2src[BATCH * NNODES];
__device__ float g_s2dst[BATCH * NNODES];

__device__ __forceinline__ uint32_t tf32r(float x) {
    uint32_t u;
    asm("cvt.rna.tf32.f32 %0, %1;" : "=r"(u) : "f"(x));
    return u;
}
__device__ __forceinline__ void mma_tf32(float* c,
                                         uint32_t a0, uint32_t a1, uint32_t a2, uint32_t a3,
                                         uint32_t b0, uint32_t b1) {
    asm volatile("mma.sync.aligned.m16n8k8.row.col.f32.tf32.tf32.f32 "
                 "{%0,%1,%2,%3},{%4,%5,%6,%7},{%8,%9},{%0,%1,%2,%3};"
                 : "+f"(c[0]), "+f"(c[1]), "+f"(c[2]), "+f"(c[3])
                 : "r"(a0), "r"(a1), "r"(a2), "r"(a3), "r"(b0), "r"(b1));
}
__device__ __forceinline__ void mma_bf16(float* c,
                                         uint32_t a0, uint32_t a1, uint32_t a2, uint32_t a3,
                                         uint32_t b0, uint32_t b1) {
    asm volatile("mma.sync.aligned.m16n8k16.row.col.f32.bf16.bf16.f32 "
                 "{%0,%1,%2,%3},{%4,%5,%6,%7},{%8,%9},{%0,%1,%2,%3};"
                 : "+f"(c[0]), "+f"(c[1]), "+f"(c[2]), "+f"(c[3])
                 : "r"(a0), "r"(a1), "r"(a2), "r"(a3), "r"(b0), "r"(b1));
}
// split two fp32 into packed bf16 hi + bf16 lo (x in low half, y in high half)
__device__ __forceinline__ void split2(float x, float y, uint32_t& hi, uint32_t& lo) {
    __nv_bfloat162 h = __floats2bfloat162_rn(x, y);
    float rx = x - __bfloat162float(h.x);
    float ry = y - __bfloat162float(h.y);
    __nv_bfloat162 l = __floats2bfloat162_rn(rx, ry);
    hi = *(uint32_t*)&h;
    lo = *(uint32_t*)&l;
}

// ---------------- twiddle table init ----------------
__global__ void k_twinit() {
    int t = threadIdx.x;
    float ang = -6.283185307179586f * (float)t / 1024.f;
    float si, co;
    sincosf(ang, &si, &co);
    g_tw[t] = make_float2(co, si);
}

// ---------------- sinc conv (only first 1000 outputs needed) ----------------
__global__ void k_sinc(const float* __restrict__ x, const float* __restrict__ w) {
    __shared__ float sw[1024];
    __shared__ float sx[1536];
    int b = blockIdx.x / SCC, c = blockIdx.x % SCC;
    for (int i = threadIdx.x; i < 1024; i += 256) sw[i] = w[c * 1024 + i];
    for (int i = threadIdx.x; i < 1536; i += 256)
        sx[i] = (i < 1512) ? x[b * TLEN + i] : 0.f;
    __syncthreads();
    for (int t = threadIdx.x; t < NNODES; t += 256) {
        float acc = 0.f;
        for (int q = 0; q < 4; q++) {
            int p = 4 * t + q;
            int k0 = 512 - p; if (k0 < 0) k0 = 0;
            const float* xs = sx + p - 512;
            for (int k = k0; k < 1024; k++) acc = fmaf(sw[k], xs[k], acc);
        }
        g_nodes[(b * NNODES + t) * NODE_DIM + c] = acc * 0.25f;
    }
}

// ---------------- STFT: pair-packed 1024-pt FFT, padded twiddle table --------
__device__ __forceinline__ int reflect_idx(int m) {
    if (m < 0) m = -m;
    else if (m >= TLEN) m = 2 * TLEN - 2 - m;
    return m;
}
#define TWP(i) ((i) + ((i) >> 4))
__global__ void k_stft(const float* __restrict__ x) {
    __shared__ float re[1024], im[1024];
    __shared__ float2 tw[544];      // padded: entry k at k + (k>>4)
    int b = blockIdx.x / 126, p = blockIdx.x % 126;
    int t = threadIdx.x;
    tw[TWP(t)] = g_tw[t];
    int fr1 = 2 * p;
    int has2 = (p < 125);
    int base1 = fr1 * 256 - 512;
    for (int n = t; n < 1024; n += 512) {
        int m1 = reflect_idx(base1 + n);
        float v1 = x[b * TLEN + m1];
        float v2 = 0.f;
        if (has2) {
            int m2 = reflect_idx(base1 + 256 + n);
            v2 = x[b * TLEN + m2];
        }
        int r = (int)(__brev((unsigned)n) >> 22);
        re[r] = v1;
        im[r] = v2;
    }
    __syncthreads();
    int mult = 512;
    for (int len = 2; len <= 1024; len <<= 1) {
        int half = len >> 1;
        int j = t & (half - 1);
        int pos = (t / half) * len + j;
        int idx = j * mult;
        float2 wv = tw[TWP(idx)];
        float co = wv.x, si = wv.y;
        float ur = re[pos], ui = im[pos];
        float vr = re[pos + half], vi = im[pos + half];
        float tr = vr * co - vi * si;
        float ti = vr * si + vi * co;
        re[pos] = ur + tr; im[pos] = ui + ti;
        re[pos + half] = ur - tr; im[pos + half] = ui - ti;
        mult >>= 1;
        __syncthreads();
    }
    for (int k = t; k <= 512; k += 512) {
        int nk = (1024 - k) & 1023;
        float zr = re[k], zi = im[k];
        float yr = re[nk], yi = im[nk];
        float m1 = 0.5f * sqrtf((zr + yr) * (zr + yr) + (zi - yi) * (zi - yi));
        g_s[(b * NB + k) * NFR + fr1] = logf(m1 + 1e-9f);
        if (has2) {
            float m2 = 0.5f * sqrtf((zi + yi) * (zi + yi) + (yr - zr) * (yr - zr));
            g_s[(b * NB + k) * NFR + fr1 + 1] = logf(m2 + 1e-9f);
        }
    }
}

// ---------------- fused conv1 + tf32-MMA conv2 + 2x2 maxpool + scatter -------
// 256 threads = 8 warps; warp yy does one output row: M=32, N=32, K=288
#define H1_STRIDE 36
#define W2_STRIDE 36
__global__ void k_fused(const float* __restrict__ w1, const float* __restrict__ b1,
                        const float* __restrict__ g1v, const float* __restrict__ be1,
                        const float* __restrict__ w2, const float* __restrict__ b2,
                        const float* __restrict__ g2v, const float* __restrict__ be2) {
    extern __shared__ float smem[];
    uint32_t* h1t = (uint32_t*)smem;                 // [10][34][36] = 12240
    uint32_t* wt2 = (uint32_t*)(smem + 12240);       // [9][co=32][ci pad36] = 10368
    float* sst = smem + 12240 + 10368;               // [12][36] = 432
    float* w1s = sst + 432;                          // 288
    float* pm = smem;                                // reuse: [8][32][33] = 8448

    int x0 = blockIdx.x * 32, y0 = blockIdx.y * 8, b = blockIdx.z;
    int tid = threadIdx.x;

    for (int i = tid; i < 9216; i += 256) {
        int ci = i & 31; int rest = i >> 5;
        int co = rest & 31; int kyx = rest >> 5;
        wt2[(kyx * 32 + co) * W2_STRIDE + ci] = tf32r(w2[(co * 32 + ci) * 9 + kyx]);
    }
    for (int i = tid; i < 288; i += 256) w1s[i] = w1[i];
    for (int i = tid; i < 12 * 36; i += 256) {
        int cc = i % 36, rr = i / 36;
        int gy = y0 - 2 + rr, gx = x0 - 2 + cc;
        float v = 0.f;
        if (gy >= 0 && gy < NB && gx >= 0 && gx < NFR)
            v = g_s[(b * NB + gy) * NFR + gx];
        sst[i] = v;
    }
    __syncthreads();

    {
        int ci = tid & 31;
        float cb1 = b1[ci];
        float sc1 = g1v[ci] * rsqrtf(1.f + EPSV);
        float bb1 = be1[ci];
        const float* wp = w1s + ci * 9;
        for (int r = tid >> 5; r < 340; r += 8) {
            int cc = r % 34, rr = r / 34;
            int y = y0 - 1 + rr, xg = x0 - 1 + cc;
            float v = 0.f;
            if (y >= 0 && y < NB && xg >= 0 && xg < NFR) {
                float acc = cb1;
#pragma unroll
                for (int ky = 0; ky < 3; ky++)
#pragma unroll
                    for (int kx = 0; kx < 3; kx++)
                        acc = fmaf(wp[ky * 3 + kx], sst[(rr + ky) * 36 + (cc + kx)], acc);
                acc = acc * sc1 + bb1;
                v = acc > 0.f ? acc : 0.f;
            }
            h1t[(rr * 34 + cc) * H1_STRIDE + ci] = tf32r(v);
        }
    }
    __syncthreads();

    int warp = tid >> 5, lane = tid & 31;
    int gid = lane >> 2, tig = lane & 3;
    int yy = warp;
    float c[2][4][4] = {};
    int abase = (yy * 34 + gid) * H1_STRIDE + tig;
#pragma unroll
    for (int ky = 0; ky < 3; ky++) {
#pragma unroll
        for (int kx = 0; kx < 3; kx++) {
            int kyx = ky * 3 + kx;
            int aoff0 = abase + (ky * 34 + kx) * H1_STRIDE;
            int boff0 = (kyx * 32 + gid) * W2_STRIDE + tig;
#pragma unroll
            for (int kc = 0; kc < 4; kc++) {
                uint32_t a[2][4], bf[4][2];
#pragma unroll
                for (int mt = 0; mt < 2; mt++) {
                    int ao = aoff0 + mt * 16 * H1_STRIDE + kc * 8;
                    a[mt][0] = h1t[ao];
                    a[mt][1] = h1t[ao + 8 * H1_STRIDE];
                    a[mt][2] = h1t[ao + 4];
                    a[mt][3] = h1t[ao + 8 * H1_STRIDE + 4];
                }
#pragma unroll
                for (int nt = 0; nt < 4; nt++) {
                    int bo = boff0 + nt * 8 * W2_STRIDE + kc * 8;
                    bf[nt][0] = wt2[bo];
                    bf[nt][1] = wt2[bo + 4];
                }
#pragma unroll
                for (int mt = 0; mt < 2; mt++)
#pragma unroll
                    for (int nt = 0; nt < 4; nt++)
                        mma_tf32(c[mt][nt], a[mt][0], a[mt][1], a[mt][2], a[mt][3],
                                 bf[nt][0], bf[nt][1]);
            }
        }
    }
    __syncthreads();

    float rs = rsqrtf(1.f + EPSV);
#pragma unroll
    for (int nt = 0; nt < 4; nt++) {
        int co0 = nt * 8 + tig * 2;
        float cb0 = b2[co0], sc0 = g2v[co0] * rs, bb0 = be2[co0];
        float cb1v = b2[co0 + 1], sc1v = g2v[co0 + 1] * rs, bb1v = be2[co0 + 1];
#pragma unroll
        for (int mt = 0; mt < 2; mt++) {
            int xa = mt * 16 + gid;
            int xbp = xa + 8;
            float v0 = fmaxf((c[mt][nt][0] + cb0) * sc0 + bb0, 0.f);
            float v1 = fmaxf((c[mt][nt][1] + cb1v) * sc1v + bb1v, 0.f);
            float v2 = fmaxf((c[mt][nt][2] + cb0) * sc0 + bb0, 0.f);
            float v3 = fmaxf((c[mt][nt][3] + cb1v) * sc1v + bb1v, 0.f);
            pm[(yy * 32 + xa) * 33 + co0] = v0;
            pm[(yy * 32 + xa) * 33 + co0 + 1] = v1;
            pm[(yy * 32 + xbp) * 33 + co0] = v2;
            pm[(yy * 32 + xbp) * 33 + co0 + 1] = v3;
        }
    }
    __syncthreads();

    int co = tid & 31, txh = tid >> 5;
#pragma unroll
    for (int t2 = 0; t2 < 2; t2++) {
        int txp = txh * 2 + t2;
        int tp = (x0 >> 1) + txp;
        if (tp < 125) {
            float4 v;
#pragma unroll
            for (int fy = 0; fy < 4; fy++) {
                int yA = 2 * fy, yB = 2 * fy + 1;
                float m0 = fmaxf(pm[(yA * 32 + 2 * txp) * 33 + co],
                                 pm[(yA * 32 + 2 * txp + 1) * 33 + co]);
                float m1 = fmaxf(pm[(yB * 32 + 2 * txp) * 33 + co],
                                 pm[(yB * 32 + 2 * txp + 1) * 33 + co]);
                ((float*)&v)[fy] = fmaxf(m0, m1);
            }
            int t = 2 * tp + (co >> 4);
            long off = (long)(b * NNODES + t) * NODE_DIM + SCC + (co & 15) * 256 + (y0 >> 1);
            *(float4*)(g_nodes + off) = v;
        }
    }
}

// ---------------- gemm1: 3-term bf16 split (Ootomo), 128x64, double-buffered -
#define APB 12
#define BPB 72
#define ASZ 1536
#define BSZ 576
__global__ void k_gemm1_t(const float* __restrict__ Wg) {
    extern __shared__ uint32_t gsm[];
    uint32_t* AhB = gsm;                         // [2][ASZ]
    uint32_t* AlB = gsm + 2 * ASZ;
    uint32_t* BhB = gsm + 4 * ASZ;               // [2][BSZ]
    uint32_t* BlB = gsm + 4 * ASZ + 2 * BSZ;
    const int M = BATCH * NNODES, N = 512, K = NODE_DIM;
    const int KT = (K + 15) / 16;                // 258
    int bx = blockIdx.x, by = blockIdx.y;
    int tid = threadIdx.x;
    int warp = tid >> 5, lane = tid & 31;
    int gid = lane >> 2, tig = lane & 3;
    int wm = (warp >> 1) * 32, wn = (warp & 1) * 32;
    float c[2][4][4] = {};

#pragma unroll
    for (int j = 0; j < 4; j++) {
        int i = tid + j * 256;
        int m = i >> 3, kp = i & 7;
        int gm = by * 128 + m;
        float2 v = make_float2(0.f, 0.f);
        if (gm < M) v = *(const float2*)(g_nodes + (long)gm * K + 2 * kp);
        uint32_t hi, lo;
        split2(v.x, v.y, hi, lo);
        AhB[m * APB + kp] = hi;
        AlB[m * APB + kp] = lo;
    }
#pragma unroll
    for (int j = 0; j < 2; j++) {
        int i = tid + j * 256;
        int kp = i >> 6, n = i & 63;
        float v0 = Wg[(long)(2 * kp) * N + bx * 64 + n];
        float v1 = Wg[(long)(2 * kp + 1) * N + bx * 64 + n];
        uint32_t hi, lo;
        split2(v0, v1, hi, lo);
        BhB[kp * BPB + n] = hi;
        BlB[kp * BPB + n] = lo;
    }
    __syncthreads();

    for (int kt = 0; kt < KT; kt++) {
        int buf = kt & 1;
        uint32_t* ah_ = AhB + buf * ASZ;
        uint32_t* al_ = AlB + buf * ASZ;
        uint32_t* bh_ = BhB + buf * BSZ;
        uint32_t* bl_ = BlB + buf * BSZ;
        float2 ra[4];
        float rb0[2], rb1[2];
        if (kt + 1 < KT) {
            int k0n = (kt + 1) * 16;
#pragma unroll
            for (int j = 0; j < 4; j++) {
                int i = tid + j * 256;
                int m = i >> 3, kp = i & 7;
                int gm = by * 128 + m, gk = k0n + 2 * kp;
                ra[j] = make_float2(0.f, 0.f);
                if (gm < M && gk < K)
                    ra[j] = *(const float2*)(g_nodes + (long)gm * K + gk);
            }
#pragma unroll
            for (int j = 0; j < 2; j++) {
                int i = tid + j * 256;
                int kp = i >> 6, n = i & 63;
                int gk = k0n + 2 * kp;
                rb0[j] = 0.f; rb1[j] = 0.f;
                if (gk < K) {
                    rb0[j] = Wg[(long)gk * N + bx * 64 + n];
                    rb1[j] = Wg[(long)(gk + 1) * N + bx * 64 + n];
                }
            }
        }
        {
            uint32_t ah[2][4], al[2][4], bh[4][2], bl[4][2];
#pragma unroll
            for (int mi = 0; mi < 2; mi++) {
                int b0 = (wm + mi * 16 + gid) * APB;
                int b1 = (wm + mi * 16 + gid + 8) * APB;
                ah[mi][0] = ah_[b0 + tig]; ah[mi][1] = ah_[b1 + tig];
                ah[mi][2] = ah_[b0 + tig + 4]; ah[mi][3] = ah_[b1 + tig + 4];
                al[mi][0] = al_[b0 + tig]; al[mi][1] = al_[b1 + tig];
                al[mi][2] = al_[b0 + tig + 4]; al[mi][3] = al_[b1 + tig + 4];
            }
#pragma unroll
            for (int ni = 0; ni < 4; ni++) {
                int nb = wn + ni * 8 + gid;
                bh[ni][0] = bh_[tig * BPB + nb];
                bh[ni][1] = bh_[(tig + 4) * BPB + nb];
                bl[ni][0] = bl_[tig * BPB + nb];
                bl[ni][1] = bl_[(tig + 4) * BPB + nb];
            }
#pragma unroll
            for (int mi = 0; mi < 2; mi++)
#pragma unroll
                for (int ni = 0; ni < 4; ni++) {
                    mma_bf16(c[mi][ni], ah[mi][0], ah[mi][1], ah[mi][2], ah[mi][3],
                             bl[ni][0], bl[ni][1]);
                    mma_bf16(c[mi][ni], al[mi][0], al[mi][1], al[mi][2], al[mi][3],
                             bh[ni][0], bh[ni][1]);
                    mma_bf16(c[mi][ni], ah[mi][0], ah[mi][1], ah[mi][2], ah[mi][3],
                             bh[ni][0], bh[ni][1]);
                }
        }
        if (kt + 1 < KT) {
            int nb2 = (kt + 1) & 1;
            uint32_t* ah2 = AhB + nb2 * ASZ;
            uint32_t* al2 = AlB + nb2 * ASZ;
            uint32_t* bh2 = BhB + nb2 * BSZ;
            uint32_t* bl2 = BlB + nb2 * BSZ;
#pragma unroll
            for (int j = 0; j < 4; j++) {
                int i = tid + j * 256;
                int m = i >> 3, kp = i & 7;
                uint32_t hi, lo;
                split2(ra[j].x, ra[j].y, hi, lo);
                ah2[m * APB + kp] = hi;
                al2[m * APB + kp] = lo;
            }
#pragma unroll
            for (int j = 0; j < 2; j++) {
                int i = tid + j * 256;
                int kp = i >> 6, n = i & 63;
                uint32_t hi, lo;
                split2(rb0[j], rb1[j], hi, lo);
                bh2[kp * BPB + n] = hi;
                bl2[kp * BPB + n] = lo;
            }
        }
        __syncthreads();
    }
#pragma unroll
    for (int mi = 0; mi < 2; mi++) {
        int r0 = by * 128 + wm + mi * 16 + gid;
        int r1 = r0 + 8;
#pragma unroll
        for (int ni = 0; ni < 4; ni++) {
            int gcol = bx * 64 + wn + ni * 8 + tig * 2;
            if (r0 < M) {
                float2 v = {c[mi][ni][0], c[mi][ni][1]};
                *(float2*)(g_gh + (long)r0 * N + gcol) = v;
            }
            if (r1 < M) {
                float2 v = {c[mi][ni][2], c[mi][ni][3]};
                *(float2*)(g_gh + (long)r1 * N + gcol) = v;
            }
        }
    }
}

// ---------------- generic tiled SGEMM (64x64x16) body ------------------------
__device__ __forceinline__ void gemm_body(const float* __restrict__ A,
                                          const float* __restrict__ B,
                                          float* __restrict__ C,
                                          int M, int N, int K) {
    __shared__ float As[16][65];
    __shared__ float Bs[16][64];
    int bx = blockIdx.x, by = blockIdx.y;
    int tid = threadIdx.x;
    int tr = tid >> 4, tc = tid & 15;
    float acc[4][4] = {};
    for (int k0 = 0; k0 < K; k0 += 16) {
        for (int i = tid; i < 64 * 16; i += 256) {
            int m = i >> 4, kk = i & 15;
            int gm = by * 64 + m, gk = k0 + kk;
            As[kk][m] = (gm < M && gk < K) ? A[(long)gm * K + gk] : 0.f;
        }
        for (int i = tid; i < 16 * 64; i += 256) {
            int kk = i >> 6, n = i & 63;
            int gk = k0 + kk, gn = bx * 64 + n;
            Bs[kk][n] = (gk < K && gn < N) ? B[(long)gk * N + gn] : 0.f;
        }
        __syncthreads();
#pragma unroll
        for (int kk = 0; kk < 16; kk++) {
            float a[4], bv[4];
#pragma unroll
            for (int i = 0; i < 4; i++) a[i] = As[kk][tr * 4 + i];
#pragma unroll
            for (int jq = 0; jq < 4; jq++) bv[jq] = Bs[kk][tc * 4 + jq];
#pragma unroll
            for (int i = 0; i < 4; i++)
#pragma unroll
                for (int jq = 0; jq < 4; jq++)
                    acc[i][jq] = fmaf(a[i], bv[jq], acc[i][jq]);
        }
        __syncthreads();
    }
    for (int i = 0; i < 4; i++) {
        int gm = by * 64 + tr * 4 + i;
        if (gm >= M) continue;
        for (int jq = 0; jq < 4; jq++) {
            int gn = bx * 64 + tc * 4 + jq;
            if (gn < N) C[(long)gm * N + gn] = acc[i][jq];
        }
    }
}

// ---------------- gemm2 + fused GAT2 scores ----------------
__global__ void k_gemm2(const float* __restrict__ W,
                        const float* __restrict__ asrc, const float* __restrict__ adst) {
    gemm_body(g_g1, W, g_h2g, BATCH * NNODES, 32, 512);
    __syncthreads();
    int tid = threadIdx.x;
    if (tid < 64) {
        int r = blockIdx.y * 64 + tid;
        if (r < BATCH * NNODES) {
            const float* hp = g_h2g + (long)r * 32;
            float s1 = 0.f, s2 = 0.f;
#pragma unroll
            for (int f = 0; f < 32; f++) {
                float v = hp[f];
                s1 = fmaf(v, asrc[f], s1);
                s2 = fmaf(v, adst[f], s2);
            }
            g_s2src[r] = s1;
            g_s2dst[r] = s2;
        }
    }
}

// ---------------- GAT1 attention scores ----------------
__global__ void k_scores1(const float* __restrict__ asrc, const float* __restrict__ adst) {
    int idx = blockIdx.x * 256 + threadIdx.x;
    if (idx >= BATCH * NNODES * 8) return;
    int h = idx & 7;
    int bn = idx >> 3;
    const float* hp = g_gh + (long)bn * 512 + h * 64;
    float s1 = 0.f, s2 = 0.f;
    for (int f = 0; f < 64; f++) {
        float v = hp[f];
        s1 = fmaf(v, asrc[h * 64 + f], s1);
        s2 = fmaf(v, adst[h * 64 + f], s2);
    }
    g_ssrc[idx] = s1;
    g_sdst[idx] = s2;
}

// ---------------- GAT1 softmax-attention + aggregate (10 i per block) --------
__global__ void k_att1(const float* __restrict__ bias) {
    extern __shared__ float sm[];
    float* swj = sm;               // [10][250][8] = 20000
    float* ss = sm + 20000;        // 2000
    float* sums = sm + 22000;      // 80
    int b = blockIdx.x / 25, ig = blockIdx.x % 25;
    int i0 = ig * 10;
    int tid = threadIdx.x;
    for (int i = tid; i < 2000; i += 256) ss[i] = g_ssrc[b * 2000 + i];
    __syncthreads();
    int warp = tid >> 5, lane = tid & 31;
    for (int task = warp; task < 80; task += 8) {
        int ii = task >> 3, h = task & 7;
        float d = g_sdst[(b * NNODES + i0 + ii) * 8 + h];
        float mx = -1e30f;
        for (int j = lane; j < NNODES; j += 32) {
            float e = d + ss[j * 8 + h];
            e = e > 0.f ? e : 0.2f * e;
            mx = fmaxf(mx, e);
        }
#pragma unroll
        for (int o = 16; o; o >>= 1) mx = fmaxf(mx, __shfl_xor_sync(0xffffffffu, mx, o));
        float smv = 0.f;
        for (int j = lane; j < NNODES; j += 32) {
            float e = d + ss[j * 8 + h];
            e = e > 0.f ? e : 0.2f * e;
            float wv = expf(e - mx);
            swj[(ii * NNODES + j) * 8 + h] = wv;
            smv += wv;
        }
#pragma unroll
        for (int o = 16; o; o >>= 1) smv += __shfl_xor_sync(0xffffffffu, smv, o);
        if (!lane) sums[ii * 8 + h] = smv;
    }
    __syncthreads();
    float acc0[10], acc1[10];
#pragma unroll
    for (int ii = 0; ii < 10; ii++) { acc0[ii] = 0.f; acc1[ii] = 0.f; }
    const float* Hb = g_gh + (long)b * NNODES * 512;
    int f0 = tid, f1 = tid + 256;
    int h0 = f0 >> 6, h1 = f1 >> 6;
    for (int j = 0; j < NNODES; j++) {
        float v0 = Hb[j * 512 + f0];
        float v1 = Hb[j * 512 + f1];
#pragma unroll
        for (int ii = 0; ii < 10; ii++) {
            acc0[ii] = fmaf(swj[(ii * NNODES + j) * 8 + h0], v0, acc0[ii]);
            acc1[ii] = fmaf(swj[(ii * NNODES + j) * 8 + h1], v1, acc1[ii]);
        }
    }
    float bi0 = bias[f0], bi1 = bias[f1];
    for (int ii = 0; ii < 10; ii++) {
        int i = i0 + ii;
        float* op = g_g1 + (long)(b * NNODES + i) * 512;
        float o0 = acc0[ii] / sums[ii * 8 + h0] + bi0;
        float o1 = acc1[ii] / sums[ii * 8 + h1] + bi1;
        op[f0] = o0 > 0.f ? o0 : 0.f;
        op[f1] = o1 > 0.f ? o1 : 0.f;
    }
}

// ---------------- GAT2 attention + aggregate + mean-pool + FC head -----------
__global__ void k_att2(const float* __restrict__ bias,
                       const float* __restrict__ fc1w, const float* __restrict__ fc1b,
                       const float* __restrict__ bg, const float* __restrict__ bb2,
                       const float* __restrict__ fc2w, const float* __restrict__ fc2b,
                       float* __restrict__ out, int write_emb) {
    extern __shared__ float am[];
    float* sh = am;                // [250*32] = 8000
    float* ssr = am + 8000;        // 256
    float* wjs = am + 8256;        // [8][250] = 2000
    float* sout = am + 10256;      // [250*32] = 8000
    float* sz = am + 18256;        // 128
    int b = blockIdx.x;
    int tid = threadIdx.x, warp = tid >> 5, lane = tid & 31;
    for (int i = tid; i < NNODES * 32; i += 256) sh[i] = g_h2g[b * NNODES * 32 + i];
    for (int i = tid; i < NNODES; i += 256) ssr[i] = g_s2src[b * NNODES + i];
    __syncthreads();
    float bi = bias[lane];
    for (int i = warp; i < NNODES; i += 8) {
        float d = g_s2dst[b * NNODES + i];
        float mx = -1e30f;
        for (int j = lane; j < NNODES; j += 32) {
            float e = d + ssr[j];
            e = e > 0.f ? e : 0.2f * e;
            mx = fmaxf(mx, e);
        }
#pragma unroll
        for (int o = 16; o; o >>= 1) mx = fmaxf(mx, __shfl_xor_sync(0xffffffffu, mx, o));
        float sum = 0.f;
        for (int j = lane; j < NNODES; j += 32) {
            float e = d + ssr[j];
            e = e > 0.f ? e : 0.2f * e;
            float wv = expf(e - mx);
            wjs[warp * NNODES + j] = wv;
            sum += wv;
        }
#pragma unroll
        for (int o = 16; o; o >>= 1) sum += __shfl_xor_sync(0xffffffffu, sum, o);
        __syncwarp();
        float acc = 0.f;
        for (int j = 0; j < NNODES; j++) acc = fmaf(wjs[warp * NNODES + j], sh[j * 32 + lane], acc);
        sout[i * 32 + lane] = acc / sum + bi;
    }
    __syncthreads();
    if (tid < 32) {
        float s = 0.f;
        for (int i = 0; i < NNODES; i++) s += sout[i * 32 + tid];
        s *= (1.f / 250.f);
        ssr[tid] = s;
        if (write_emb) out[16 + b * 32 + tid] = s;
    }
    __syncthreads();
    if (tid < 128) {
        float z = fc1b[tid];
        for (int f = 0; f < 32; f++) z = fmaf(ssr[f], fc1w[f * 128 + tid], z);
        z = z * (bg[tid] * rsqrtf(1.f + EPSV)) + bb2[tid];
        sz[tid] = z > 0.f ? z : 0.f;
    }
    __syncthreads();
    if (tid < 2) {
        float o = fc2b[tid];
        for (int q = 0; q < 128; q++) o = fmaf(sz[q], fc2w[q * 2 + tid], o);
        out[b * 2 + tid] = o;
    }
}

extern "C" void kernel_launch(void* const* d_in, const int* in_sizes, int n_in,
                              void* d_out, int out_size) {
    const float* x = (const float*)d_in[0];
    const float* sinc_w = (const float*)d_in[1];
    const float* conv1_w = (const float*)d_in[2];
    const float* conv1_b = (const float*)d_in[3];
    const float* bn1_g = (const float*)d_in[4];
    const float* bn1_b = (const float*)d_in[5];
    const float* conv2_w = (const float*)d_in[6];
    const float* conv2_b = (const float*)d_in[7];
    const float* bn2_g = (const float*)d_in[8];
    const float* bn2_b = (const float*)d_in[9];
    const float* gat1_W = (const float*)d_in[10];
    const float* gat1_asrc = (const float*)d_in[11];
    const float* gat1_adst = (const float*)d_in[12];
    const float* gat1_bias = (const float*)d_in[13];
    const float* gat2_W = (const float*)d_in[14];
    const float* gat2_asrc = (const float*)d_in[15];
    const float* gat2_adst = (const float*)d_in[16];
    const float* gat2_bias = (const float*)d_in[17];
    const float* fc1_w = (const float*)d_in[18];
    const float* fc1_b = (const float*)d_in[19];
    const float* bnf_g = (const float*)d_in[20];
    const float* bnf_b = (const float*)d_in[21];
    const float* fc2_w = (const float*)d_in[22];
    const float* fc2_b = (const float*)d_in[23];

    const int FUSED_SMEM = 23328 * 4;
    const int GEMM1_SMEM = (4 * ASZ + 4 * BSZ) * 4;   // 33792 B
    const int ATT2_SMEM = 18384 * 4;
    cudaFuncSetAttribute(k_fused, cudaFuncAttributeMaxDynamicSharedMemorySize, FUSED_SMEM);
    cudaFuncSetAttribute(k_gemm1_t, cudaFuncAttributeMaxDynamicSharedMemorySize, GEMM1_SMEM);
    cudaFuncSetAttribute(k_att1, cudaFuncAttributeMaxDynamicSharedMemorySize, 22080 * 4);
    cudaFuncSetAttribute(k_att2, cudaFuncAttributeMaxDynamicSharedMemorySize, ATT2_SMEM);

    k_twinit<<<1, 512>>>();
    k_sinc<<<BATCH * SCC, 256>>>(x, sinc_w);
    k_stft<<<BATCH * 126, 512>>>(x);

    dim3 gf(8, 64, BATCH);
    k_fused<<<gf, 256, FUSED_SMEM>>>(conv1_w, conv1_b, bn1_g, bn1_b,
                                     conv2_w, conv2_b, bn2_g, bn2_b);

    dim3 gg1(8, 16);
    k_gemm1_t<<<gg1, 256, GEMM1_SMEM>>>(gat1_W);
    k_scores1<<<(BATCH * NNODES * 8 + 255) / 256, 256>>>(gat1_asrc, gat1_adst);
    k_att1<<<BATCH * 25, 256, 22080 * 4>>>(gat1_bias);

    dim3 gg2(1, 32);
    k_gemm2<<<gg2, 256>>>(gat2_W, gat2_asrc, gat2_adst);

    int write_emb = (out_size >= 272) ? 1 : 0;
    k_att2<<<BATCH, 256, ATT2_SMEM>>>(gat2_bias, fc1_w, fc1_b, bnf_g, bnf_b,
                                      fc2_w, fc2_b, (float*)d_out, write_emb);
}

// round 12
// speedup vs baseline: 1.1272x; 1.0047x over previous
#include <cuda_runtime.h>
#include <cuda_bf16.h>
#include <cstdint>

#define BATCH 8
#define TLEN 64000
#define NFR 251
#define NB 513
#define NCH 32
#define NNODES 250
#define NODE_DIM 4116
#define SCC 20
#define EPSV 1e-5f

// ---------------- scratch (device globals; no allocation) ----------------
__device__ float g_s[BATCH * NB * NFR];
__device__ float2 g_tw[768];
__device__ float g_nodes[BATCH * NNODES * NODE_DIM];
__device__ float g_gh[BATCH * NNODES * 512];
__device__ float g_ssrc[BATCH * NNODES * 8];
__device__ float g_sdst[BATCH * NNODES * 8];
__device__ float g_g1[BATCH * NNODES * 512];
__device__ float g_h2g[BATCH * NNODES * 32];
__device__ float g_s2src[BATCH * NNODES];
__device__ float g_s2dst[BATCH * NNODES];

__device__ __forceinline__ uint32_t tf32r(float x) {
    uint32_t u;
    asm("cvt.rna.tf32.f32 %0, %1;" : "=r"(u) : "f"(x));
    return u;
}
__device__ __forceinline__ void mma_tf32(float* c,
                                         uint32_t a0, uint32_t a1, uint32_t a2, uint32_t a3,
                                         uint32_t b0, uint32_t b1) {
    asm volatile("mma.sync.aligned.m16n8k8.row.col.f32.tf32.tf32.f32 "
                 "{%0,%1,%2,%3},{%4,%5,%6,%7},{%8,%9},{%0,%1,%2,%3};"
                 : "+f"(c[0]), "+f"(c[1]), "+f"(c[2]), "+f"(c[3])
                 : "r"(a0), "r"(a1), "r"(a2), "r"(a3), "r"(b0), "r"(b1));
}
__device__ __forceinline__ void mma_bf16(float* c,
                                         uint32_t a0, uint32_t a1, uint32_t a2, uint32_t a3,
                                         uint32_t b0, uint32_t b1) {
    asm volatile("mma.sync.aligned.m16n8k16.row.col.f32.bf16.bf16.f32 "
                 "{%0,%1,%2,%3},{%4,%5,%6,%7},{%8,%9},{%0,%1,%2,%3};"
                 : "+f"(c[0]), "+f"(c[1]), "+f"(c[2]), "+f"(c[3])
                 : "r"(a0), "r"(a1), "r"(a2), "r"(a3), "r"(b0), "r"(b1));
}
// split two fp32 into packed bf16 hi + bf16 lo (x in low half, y in high half)
__device__ __forceinline__ void split2(float x, float y, uint32_t& hi, uint32_t& lo) {
    __nv_bfloat162 h = __floats2bfloat162_rn(x, y);
    float rx = x - __bfloat162float(h.x);
    float ry = y - __bfloat162float(h.y);
    __nv_bfloat162 l = __floats2bfloat162_rn(rx, ry);
    hi = *(uint32_t*)&h;
    lo = *(uint32_t*)&l;
}

// ---------------- twiddle table init (768 entries for radix-4) --------------
__global__ void k_twinit() {
    int t = threadIdx.x;
    if (t < 768) {
        float ang = -6.283185307179586f * (float)t / 1024.f;
        float si, co;
        sincosf(ang, &si, &co);
        g_tw[t] = make_float2(co, si);
    }
}

// ---------------- sinc conv (only first 1000 outputs needed) ----------------
__global__ void k_sinc(const float* __restrict__ x, const float* __restrict__ w) {
    __shared__ float sw[1024];
    __shared__ float sx[1536];
    int b = blockIdx.x / SCC, c = blockIdx.x % SCC;
    for (int i = threadIdx.x; i < 1024; i += 256) sw[i] = w[c * 1024 + i];
    for (int i = threadIdx.x; i < 1536; i += 256)
        sx[i] = (i < 1512) ? x[b * TLEN + i] : 0.f;
    __syncthreads();
    for (int t = threadIdx.x; t < NNODES; t += 256) {
        float acc = 0.f;
        for (int q = 0; q < 4; q++) {
            int p = 4 * t + q;
            int k0 = 512 - p; if (k0 < 0) k0 = 0;
            const float* xs = sx + p - 512;
            for (int k = k0; k < 1024; k++) acc = fmaf(sw[k], xs[k], acc);
        }
        g_nodes[(b * NNODES + t) * NODE_DIM + c] = acc * 0.25f;
    }
}

// ---------------- STFT: pair-packed radix-4 1024-pt FFT ----------------------
__device__ __forceinline__ int reflect_idx(int m) {
    if (m < 0) m = -m;
    else if (m >= TLEN) m = 2 * TLEN - 2 - m;
    return m;
}
#define TWP(i) ((i) + ((i) >> 4))
__global__ void k_stft(const float* __restrict__ x) {
    __shared__ float re[1024], im[1024];
    __shared__ float2 tw[816];      // 768 entries, padded at k + (k>>4)
    int b = blockIdx.x / 126, p = blockIdx.x % 126;
    int t = threadIdx.x;            // 0..255
    for (int i = t; i < 768; i += 256) tw[TWP(i)] = g_tw[i];
    int fr1 = 2 * p;
    int has2 = (p < 125);
    int base1 = fr1 * 256 - 512;
    // load with base-4 digit reversal (bit-reverse then swap adjacent bit pairs)
    for (int n = t; n < 1024; n += 256) {
        int m1 = reflect_idx(base1 + n);
        float v1 = x[b * TLEN + m1];
        float v2 = 0.f;
        if (has2) {
            int m2 = reflect_idx(base1 + 256 + n);
            v2 = x[b * TLEN + m2];
        }
        int br = (int)(__brev((unsigned)n) >> 22);
        int r4 = ((br & 0x155) << 1) | ((br & 0x2AA) >> 1);
        re[r4] = v1;
        im[r4] = v2;
    }
    __syncthreads();
    // 5 radix-4 stages
    int m = 256;
#pragma unroll
    for (int L = 4; L <= 1024; L <<= 2) {
        int q = L >> 2;
        int j = t & (q - 1);
        int pos = (t / q) * L + j;
        int i1 = j * m;
        float2 w1 = tw[TWP(i1)];
        float2 w2 = tw[TWP(2 * i1)];
        float2 w3 = tw[TWP(3 * i1)];
        float ar = re[pos],         ai = im[pos];
        float xr = re[pos + q],     xi = im[pos + q];
        float cr = re[pos + 2 * q], ci = im[pos + 2 * q];
        float dr = re[pos + 3 * q], di = im[pos + 3 * q];
        float b_r = xr * w1.x - xi * w1.y, b_i = xr * w1.y + xi * w1.x;
        float c_r = cr * w2.x - ci * w2.y, c_i = cr * w2.y + ci * w2.x;
        float d_r = dr * w3.x - di * w3.y, d_i = dr * w3.y + di * w3.x;
        float t0r = ar + c_r, t0i = ai + c_i;
        float t1r = ar - c_r, t1i = ai - c_i;
        float t2r = b_r + d_r, t2i = b_i + d_i;
        float t3r = b_i - d_i, t3i = d_r - b_r;   // -i*(b-d)
        re[pos]         = t0r + t2r; im[pos]         = t0i + t2i;
        re[pos + q]     = t1r + t3r; im[pos + q]     = t1i + t3i;
        re[pos + 2 * q] = t0r - t2r; im[pos + 2 * q] = t0i - t2i;
        re[pos + 3 * q] = t1r - t3r; im[pos + 3 * q] = t1i - t3i;
        m >>= 2;
        __syncthreads();
    }
    // unpack two real spectra
    for (int k = t; k <= 512; k += 256) {
        int nk = (1024 - k) & 1023;
        float zr = re[k], zi = im[k];
        float yr = re[nk], yi = im[nk];
        float m1 = 0.5f * sqrtf((zr + yr) * (zr + yr) + (zi - yi) * (zi - yi));
        g_s[(b * NB + k) * NFR + fr1] = logf(m1 + 1e-9f);
        if (has2) {
            float m2 = 0.5f * sqrtf((zi + yi) * (zi + yi) + (yr - zr) * (yr - zr));
            g_s[(b * NB + k) * NFR + fr1 + 1] = logf(m2 + 1e-9f);
        }
    }
}

// ---------------- fused conv1 + tf32-MMA conv2 + 2x2 maxpool + scatter -------
// 256 threads = 8 warps; warp yy does one output row: M=32, N=32, K=288
#define H1_STRIDE 36
#define W2_STRIDE 36
__global__ void k_fused(const float* __restrict__ w1, const float* __restrict__ b1,
                        const float* __restrict__ g1v, const float* __restrict__ be1,
                        const float* __restrict__ w2, const float* __restrict__ b2,
                        const float* __restrict__ g2v, const float* __restrict__ be2) {
    extern __shared__ float smem[];
    uint32_t* h1t = (uint32_t*)smem;                 // [10][34][36] = 12240
    uint32_t* wt2 = (uint32_t*)(smem + 12240);       // [9][co=32][ci pad36] = 10368
    float* sst = smem + 12240 + 10368;               // [12][36] = 432
    float* w1s = sst + 432;                          // 288
    float* pm = smem;                                // reuse: [8][32][33] = 8448

    int x0 = blockIdx.x * 32, y0 = blockIdx.y * 8, b = blockIdx.z;
    int tid = threadIdx.x;

    for (int i = tid; i < 9216; i += 256) {
        int ci = i & 31; int rest = i >> 5;
        int co = rest & 31; int kyx = rest >> 5;
        wt2[(kyx * 32 + co) * W2_STRIDE + ci] = tf32r(w2[(co * 32 + ci) * 9 + kyx]);
    }
    for (int i = tid; i < 288; i += 256) w1s[i] = w1[i];
    for (int i = tid; i < 12 * 36; i += 256) {
        int cc = i % 36, rr = i / 36;
        int gy = y0 - 2 + rr, gx = x0 - 2 + cc;
        float v = 0.f;
        if (gy >= 0 && gy < NB && gx >= 0 && gx < NFR)
            v = g_s[(b * NB + gy) * NFR + gx];
        sst[i] = v;
    }
    __syncthreads();

    {
        int ci = tid & 31;
        float cb1 = b1[ci];
        float sc1 = g1v[ci] * rsqrtf(1.f + EPSV);
        float bb1 = be1[ci];
        const float* wp = w1s + ci * 9;
        for (int r = tid >> 5; r < 340; r += 8) {
            int cc = r % 34, rr = r / 34;
            int y = y0 - 1 + rr, xg = x0 - 1 + cc;
            float v = 0.f;
            if (y >= 0 && y < NB && xg >= 0 && xg < NFR) {
                float acc = cb1;
#pragma unroll
                for (int ky = 0; ky < 3; ky++)
#pragma unroll
                    for (int kx = 0; kx < 3; kx++)
                        acc = fmaf(wp[ky * 3 + kx], sst[(rr + ky) * 36 + (cc + kx)], acc);
                acc = acc * sc1 + bb1;
                v = acc > 0.f ? acc : 0.f;
            }
            h1t[(rr * 34 + cc) * H1_STRIDE + ci] = tf32r(v);
        }
    }
    __syncthreads();

    int warp = tid >> 5, lane = tid & 31;
    int gid = lane >> 2, tig = lane & 3;
    int yy = warp;
    float c[2][4][4] = {};
    int abase = (yy * 34 + gid) * H1_STRIDE + tig;
#pragma unroll
    for (int ky = 0; ky < 3; ky++) {
#pragma unroll
        for (int kx = 0; kx < 3; kx++) {
            int kyx = ky * 3 + kx;
            int aoff0 = abase + (ky * 34 + kx) * H1_STRIDE;
            int boff0 = (kyx * 32 + gid) * W2_STRIDE + tig;
#pragma unroll
            for (int kc = 0; kc < 4; kc++) {
                uint32_t a[2][4], bf[4][2];
#pragma unroll
                for (int mt = 0; mt < 2; mt++) {
                    int ao = aoff0 + mt * 16 * H1_STRIDE + kc * 8;
                    a[mt][0] = h1t[ao];
                    a[mt][1] = h1t[ao + 8 * H1_STRIDE];
                    a[mt][2] = h1t[ao + 4];
                    a[mt][3] = h1t[ao + 8 * H1_STRIDE + 4];
                }
#pragma unroll
                for (int nt = 0; nt < 4; nt++) {
                    int bo = boff0 + nt * 8 * W2_STRIDE + kc * 8;
                    bf[nt][0] = wt2[bo];
                    bf[nt][1] = wt2[bo + 4];
                }
#pragma unroll
                for (int mt = 0; mt < 2; mt++)
#pragma unroll
                    for (int nt = 0; nt < 4; nt++)
                        mma_tf32(c[mt][nt], a[mt][0], a[mt][1], a[mt][2], a[mt][3],
                                 bf[nt][0], bf[nt][1]);
            }
        }
    }
    __syncthreads();

    float rs = rsqrtf(1.f + EPSV);
#pragma unroll
    for (int nt = 0; nt < 4; nt++) {
        int co0 = nt * 8 + tig * 2;
        float cb0 = b2[co0], sc0 = g2v[co0] * rs, bb0 = be2[co0];
        float cb1v = b2[co0 + 1], sc1v = g2v[co0 + 1] * rs, bb1v = be2[co0 + 1];
#pragma unroll
        for (int mt = 0; mt < 2; mt++) {
            int xa = mt * 16 + gid;
            int xbp = xa + 8;
            float v0 = fmaxf((c[mt][nt][0] + cb0) * sc0 + bb0, 0.f);
            float v1 = fmaxf((c[mt][nt][1] + cb1v) * sc1v + bb1v, 0.f);
            float v2 = fmaxf((c[mt][nt][2] + cb0) * sc0 + bb0, 0.f);
            float v3 = fmaxf((c[mt][nt][3] + cb1v) * sc1v + bb1v, 0.f);
            pm[(yy * 32 + xa) * 33 + co0] = v0;
            pm[(yy * 32 + xa) * 33 + co0 + 1] = v1;
            pm[(yy * 32 + xbp) * 33 + co0] = v2;
            pm[(yy * 32 + xbp) * 33 + co0 + 1] = v3;
        }
    }
    __syncthreads();

    int co = tid & 31, txh = tid >> 5;
#pragma unroll
    for (int t2 = 0; t2 < 2; t2++) {
        int txp = txh * 2 + t2;
        int tp = (x0 >> 1) + txp;
        if (tp < 125) {
            float4 v;
#pragma unroll
            for (int fy = 0; fy < 4; fy++) {
                int yA = 2 * fy, yB = 2 * fy + 1;
                float m0 = fmaxf(pm[(yA * 32 + 2 * txp) * 33 + co],
                                 pm[(yA * 32 + 2 * txp + 1) * 33 + co]);
                float m1 = fmaxf(pm[(yB * 32 + 2 * txp) * 33 + co],
                                 pm[(yB * 32 + 2 * txp + 1) * 33 + co]);
                ((float*)&v)[fy] = fmaxf(m0, m1);
            }
            int t = 2 * tp + (co >> 4);
            long off = (long)(b * NNODES + t) * NODE_DIM + SCC + (co & 15) * 256 + (y0 >> 1);
            *(float4*)(g_nodes + off) = v;
        }
    }
}

// ---------------- gemm1: 3-term bf16 split (Ootomo), 128x64, double-buffered -
#define APB 12
#define BPB 72
#define ASZ 1536
#define BSZ 576
__global__ void k_gemm1_t(const float* __restrict__ Wg) {
    extern __shared__ uint32_t gsm[];
    uint32_t* AhB = gsm;                         // [2][ASZ]
    uint32_t* AlB = gsm + 2 * ASZ;
    uint32_t* BhB = gsm + 4 * ASZ;               // [2][BSZ]
    uint32_t* BlB = gsm + 4 * ASZ + 2 * BSZ;
    const int M = BATCH * NNODES, N = 512, K = NODE_DIM;
    const int KT = (K + 15) / 16;                // 258
    int bx = blockIdx.x, by = blockIdx.y;
    int tid = threadIdx.x;
    int warp = tid >> 5, lane = tid & 31;
    int gid = lane >> 2, tig = lane & 3;
    int wm = (warp >> 1) * 32, wn = (warp & 1) * 32;
    float c[2][4][4] = {};

#pragma unroll
    for (int j = 0; j < 4; j++) {
        int i = tid + j * 256;
        int m = i >> 3, kp = i & 7;
        int gm = by * 128 + m;
        float2 v = make_float2(0.f, 0.f);
        if (gm < M) v = *(const float2*)(g_nodes + (long)gm * K + 2 * kp);
        uint32_t hi, lo;
        split2(v.x, v.y, hi, lo);
        AhB[m * APB + kp] = hi;
        AlB[m * APB + kp] = lo;
    }
#pragma unroll
    for (int j = 0; j < 2; j++) {
        int i = tid + j * 256;
        int kp = i >> 6, n = i & 63;
        float v0 = Wg[(long)(2 * kp) * N + bx * 64 + n];
        float v1 = Wg[(long)(2 * kp + 1) * N + bx * 64 + n];
        uint32_t hi, lo;
        split2(v0, v1, hi, lo);
        BhB[kp * BPB + n] = hi;
        BlB[kp * BPB + n] = lo;
    }
    __syncthreads();

    for (int kt = 0; kt < KT; kt++) {
        int buf = kt & 1;
        uint32_t* ah_ = AhB + buf * ASZ;
        uint32_t* al_ = AlB + buf * ASZ;
        uint32_t* bh_ = BhB + buf * BSZ;
        uint32_t* bl_ = BlB + buf * BSZ;
        float2 ra[4];
        float rb0[2], rb1[2];
        if (kt + 1 < KT) {
            int k0n = (kt + 1) * 16;
#pragma unroll
            for (int j = 0; j < 4; j++) {
                int i = tid + j * 256;
                int m = i >> 3, kp = i & 7;
                int gm = by * 128 + m, gk = k0n + 2 * kp;
                ra[j] = make_float2(0.f, 0.f);
                if (gm < M && gk < K)
                    ra[j] = *(const float2*)(g_nodes + (long)gm * K + gk);
            }
#pragma unroll
            for (int j = 0; j < 2; j++) {
                int i = tid + j * 256;
                int kp = i >> 6, n = i & 63;
                int gk = k0n + 2 * kp;
                rb0[j] = 0.f; rb1[j] = 0.f;
                if (gk < K) {
                    rb0[j] = Wg[(long)gk * N + bx * 64 + n];
                    rb1[j] = Wg[(long)(gk + 1) * N + bx * 64 + n];
                }
            }
        }
        {
            uint32_t ah[2][4], al[2][4], bh[4][2], bl[4][2];
#pragma unroll
            for (int mi = 0; mi < 2; mi++) {
                int b0 = (wm + mi * 16 + gid) * APB;
                int b1 = (wm + mi * 16 + gid + 8) * APB;
                ah[mi][0] = ah_[b0 + tig]; ah[mi][1] = ah_[b1 + tig];
                ah[mi][2] = ah_[b0 + tig + 4]; ah[mi][3] = ah_[b1 + tig + 4];
                al[mi][0] = al_[b0 + tig]; al[mi][1] = al_[b1 + tig];
                al[mi][2] = al_[b0 + tig + 4]; al[mi][3] = al_[b1 + tig + 4];
            }
#pragma unroll
            for (int ni = 0; ni < 4; ni++) {
                int nb = wn + ni * 8 + gid;
                bh[ni][0] = bh_[tig * BPB + nb];
                bh[ni][1] = bh_[(tig + 4) * BPB + nb];
                bl[ni][0] = bl_[tig * BPB + nb];
                bl[ni][1] = bl_[(tig + 4) * BPB + nb];
            }
#pragma unroll
            for (int mi = 0; mi < 2; mi++)
#pragma unroll
                for (int ni = 0; ni < 4; ni++) {
                    mma_bf16(c[mi][ni], ah[mi][0], ah[mi][1], ah[mi][2], ah[mi][3],
                             bl[ni][0], bl[ni][1]);
                    mma_bf16(c[mi][ni], al[mi][0], al[mi][1], al[mi][2], al[mi][3],
                             bh[ni][0], bh[ni][1]);
                    mma_bf16(c[mi][ni], ah[mi][0], ah[mi][1], ah[mi][2], ah[mi][3],
                             bh[ni][0], bh[ni][1]);
                }
        }
        if (kt + 1 < KT) {
            int nb2 = (kt + 1) & 1;
            uint32_t* ah2 = AhB + nb2 * ASZ;
            uint32_t* al2 = AlB + nb2 * ASZ;
            uint32_t* bh2 = BhB + nb2 * BSZ;
            uint32_t* bl2 = BlB + nb2 * BSZ;
#pragma unroll
            for (int j = 0; j < 4; j++) {
                int i = tid + j * 256;
                int m = i >> 3, kp = i & 7;
                uint32_t hi, lo;
                split2(ra[j].x, ra[j].y, hi, lo);
                ah2[m * APB + kp] = hi;
                al2[m * APB + kp] = lo;
            }
#pragma unroll
            for (int j = 0; j < 2; j++) {
                int i = tid + j * 256;
                int kp = i >> 6, n = i & 63;
                uint32_t hi, lo;
                split2(rb0[j], rb1[j], hi, lo);
                bh2[kp * BPB + n] = hi;
                bl2[kp * BPB + n] = lo;
            }
        }
        __syncthreads();
    }
#pragma unroll
    for (int mi = 0; mi < 2; mi++) {
        int r0 = by * 128 + wm + mi * 16 + gid;
        int r1 = r0 + 8;
#pragma unroll
        for (int ni = 0; ni < 4; ni++) {
            int gcol = bx * 64 + wn + ni * 8 + tig * 2;
            if (r0 < M) {
                float2 v = {c[mi][ni][0], c[mi][ni][1]};
                *(float2*)(g_gh + (long)r0 * N + gcol) = v;
            }
            if (r1 < M) {
                float2 v = {c[mi][ni][2], c[mi][ni][3]};
                *(float2*)(g_gh + (long)r1 * N + gcol) = v;
            }
        }
    }
}

// ---------------- generic tiled SGEMM (64x64x16) body ------------------------
__device__ __forceinline__ void gemm_body(const float* __restrict__ A,
                                          const float* __restrict__ B,
                                          float* __restrict__ C,
                                          int M, int N, int K) {
    __shared__ float As[16][65];
    __shared__ float Bs[16][64];
    int bx = blockIdx.x, by = blockIdx.y;
    int tid = threadIdx.x;
    int tr = tid >> 4, tc = tid & 15;
    float acc[4][4] = {};
    for (int k0 = 0; k0 < K; k0 += 16) {
        for (int i = tid; i < 64 * 16; i += 256) {
            int m = i >> 4, kk = i & 15;
            int gm = by * 64 + m, gk = k0 + kk;
            As[kk][m] = (gm < M && gk < K) ? A[(long)gm * K + gk] : 0.f;
        }
        for (int i = tid; i < 16 * 64; i += 256) {
            int kk = i >> 6, n = i & 63;
            int gk = k0 + kk, gn = bx * 64 + n;
            Bs[kk][n] = (gk < K && gn < N) ? B[(long)gk * N + gn] : 0.f;
        }
        __syncthreads();
#pragma unroll
        for (int kk = 0; kk < 16; kk++) {
            float a[4], bv[4];
#pragma unroll
            for (int i = 0; i < 4; i++) a[i] = As[kk][tr * 4 + i];
#pragma unroll
            for (int jq = 0; jq < 4; jq++) bv[jq] = Bs[kk][tc * 4 + jq];
#pragma unroll
            for (int i = 0; i < 4; i++)
#pragma unroll
                for (int jq = 0; jq < 4; jq++)
                    acc[i][jq] = fmaf(a[i], bv[jq], acc[i][jq]);
        }
        __syncthreads();
    }
    for (int i = 0; i < 4; i++) {
        int gm = by * 64 + tr * 4 + i;
        if (gm >= M) continue;
        for (int jq = 0; jq < 4; jq++) {
            int gn = bx * 64 + tc * 4 + jq;
            if (gn < N) C[(long)gm * N + gn] = acc[i][jq];
        }
    }
}

// ---------------- gemm2 + fused GAT2 scores ----------------
__global__ void k_gemm2(const float* __restrict__ W,
                        const float* __restrict__ asrc, const float* __restrict__ adst) {
    gemm_body(g_g1, W, g_h2g, BATCH * NNODES, 32, 512);
    __syncthreads();
    int tid = threadIdx.x;
    if (tid < 64) {
        int r = blockIdx.y * 64 + tid;
        if (r < BATCH * NNODES) {
            const float* hp = g_h2g + (long)r * 32;
            float s1 = 0.f, s2 = 0.f;
#pragma unroll
            for (int f = 0; f < 32; f++) {
                float v = hp[f];
                s1 = fmaf(v, asrc[f], s1);
                s2 = fmaf(v, adst[f], s2);
            }
            g_s2src[r] = s1;
            g_s2dst[r] = s2;
        }
    }
}

// ---------------- GAT1 attention scores ----------------
__global__ void k_scores1(const float* __restrict__ asrc, const float* __restrict__ adst) {
    int idx = blockIdx.x * 256 + threadIdx.x;
    if (idx >= BATCH * NNODES * 8) return;
    int h = idx & 7;
    int bn = idx >> 3;
    const float* hp = g_gh + (long)bn * 512 + h * 64;
    float s1 = 0.f, s2 = 0.f;
    for (int f = 0; f < 64; f++) {
        float v = hp[f];
        s1 = fmaf(v, asrc[h * 64 + f], s1);
        s2 = fmaf(v, adst[h * 64 + f], s2);
    }
    g_ssrc[idx] = s1;
    g_sdst[idx] = s2;
}

// ---------------- GAT1 softmax-attention + aggregate (10 i per block) --------
__global__ void k_att1(const float* __restrict__ bias) {
    extern __shared__ float sm[];
    float* swj = sm;               // [10][250][8] = 20000
    float* ss = sm + 20000;        // 2000
    float* sums = sm + 22000;      // 80
    int b = blockIdx.x / 25, ig = blockIdx.x % 25;
    int i0 = ig * 10;
    int tid = threadIdx.x;
    for (int i = tid; i < 2000; i += 256) ss[i] = g_ssrc[b * 2000 + i];
    __syncthreads();
    int warp = tid >> 5, lane = tid & 31;
    for (int task = warp; task < 80; task += 8) {
        int ii = task >> 3, h = task & 7;
        float d = g_sdst[(b * NNODES + i0 + ii) * 8 + h];
        float mx = -1e30f;
        for (int j = lane; j < NNODES; j += 32) {
            float e = d + ss[j * 8 + h];
            e = e > 0.f ? e : 0.2f * e;
            mx = fmaxf(mx, e);
        }
#pragma unroll
        for (int o = 16; o; o >>= 1) mx = fmaxf(mx, __shfl_xor_sync(0xffffffffu, mx, o));
        float smv = 0.f;
        for (int j = lane; j < NNODES; j += 32) {
            float e = d + ss[j * 8 + h];
            e = e > 0.f ? e : 0.2f * e;
            float wv = expf(e - mx);
            swj[(ii * NNODES + j) * 8 + h] = wv;
            smv += wv;
        }
#pragma unroll
        for (int o = 16; o; o >>= 1) smv += __shfl_xor_sync(0xffffffffu, smv, o);
        if (!lane) sums[ii * 8 + h] = smv;
    }
    __syncthreads();
    float acc0[10], acc1[10];
#pragma unroll
    for (int ii = 0; ii < 10; ii++) { acc0[ii] = 0.f; acc1[ii] = 0.f; }
    const float* Hb = g_gh + (long)b * NNODES * 512;
    int f0 = tid, f1 = tid + 256;
    int h0 = f0 >> 6, h1 = f1 >> 6;
    for (int j = 0; j < NNODES; j++) {
        float v0 = Hb[j * 512 + f0];
        float v1 = Hb[j * 512 + f1];
#pragma unroll
        for (int ii = 0; ii < 10; ii++) {
            acc0[ii] = fmaf(swj[(ii * NNODES + j) * 8 + h0], v0, acc0[ii]);
            acc1[ii] = fmaf(swj[(ii * NNODES + j) * 8 + h1], v1, acc1[ii]);
        }
    }
    float bi0 = bias[f0], bi1 = bias[f1];
    for (int ii = 0; ii < 10; ii++) {
        int i = i0 + ii;
        float* op = g_g1 + (long)(b * NNODES + i) * 512;
        float o0 = acc0[ii] / sums[ii * 8 + h0] + bi0;
        float o1 = acc1[ii] / sums[ii * 8 + h1] + bi1;
        op[f0] = o0 > 0.f ? o0 : 0.f;
        op[f1] = o1 > 0.f ? o1 : 0.f;
    }
}

// ---------------- GAT2 attention + aggregate + mean-pool + FC head -----------
__global__ void k_att2(const float* __restrict__ bias,
                       const float* __restrict__ fc1w, const float* __restrict__ fc1b,
                       const float* __restrict__ bg, const float* __restrict__ bb2,
                       const float* __restrict__ fc2w, const float* __restrict__ fc2b,
                       float* __restrict__ out, int write_emb) {
    extern __shared__ float am[];
    float* sh = am;                // [250*32] = 8000
    float* ssr = am + 8000;        // 256
    float* wjs = am + 8256;        // [8][250] = 2000
    float* sout = am + 10256;      // [250*32] = 8000
    float* sz = am + 18256;        // 128
    int b = blockIdx.x;
    int tid = threadIdx.x, warp = tid >> 5, lane = tid & 31;
    for (int i = tid; i < NNODES * 32; i += 256) sh[i] = g_h2g[b * NNODES * 32 + i];
    for (int i = tid; i < NNODES; i += 256) ssr[i] = g_s2src[b * NNODES + i];
    __syncthreads();
    float bi = bias[lane];
    for (int i = warp; i < NNODES; i += 8) {
        float d = g_s2dst[b * NNODES + i];
        float mx = -1e30f;
        for (int j = lane; j < NNODES; j += 32) {
            float e = d + ssr[j];
            e = e > 0.f ? e : 0.2f * e;
            mx = fmaxf(mx, e);
        }
#pragma unroll
        for (int o = 16; o; o >>= 1) mx = fmaxf(mx, __shfl_xor_sync(0xffffffffu, mx, o));
        float sum = 0.f;
        for (int j = lane; j < NNODES; j += 32) {
            float e = d + ssr[j];
            e = e > 0.f ? e : 0.2f * e;
            float wv = expf(e - mx);
            wjs[warp * NNODES + j] = wv;
            sum += wv;
        }
#pragma unroll
        for (int o = 16; o; o >>= 1) sum += __shfl_xor_sync(0xffffffffu, sum, o);
        __syncwarp();
        float acc = 0.f;
        for (int j = 0; j < NNODES; j++) acc = fmaf(wjs[warp * NNODES + j], sh[j * 32 + lane], acc);
        sout[i * 32 + lane] = acc / sum + bi;
    }
    __syncthreads();
    if (tid < 32) {
        float s = 0.f;
        for (int i = 0; i < NNODES; i++) s += sout[i * 32 + tid];
        s *= (1.f / 250.f);
        ssr[tid] = s;
        if (write_emb) out[16 + b * 32 + tid] = s;
    }
    __syncthreads();
    if (tid < 128) {
        float z = fc1b[tid];
        for (int f = 0; f < 32; f++) z = fmaf(ssr[f], fc1w[f * 128 + tid], z);
        z = z * (bg[tid] * rsqrtf(1.f + EPSV)) + bb2[tid];
        sz[tid] = z > 0.f ? z : 0.f;
    }
    __syncthreads();
    if (tid < 2) {
        float o = fc2b[tid];
        for (int q = 0; q < 128; q++) o = fmaf(sz[q], fc2w[q * 2 + tid], o);
        out[b * 2 + tid] = o;
    }
}

extern "C" void kernel_launch(void* const* d_in, const int* in_sizes, int n_in,
                              void* d_out, int out_size) {
    const float* x = (const float*)d_in[0];
    const float* sinc_w = (const float*)d_in[1];
    const float* conv1_w = (const float*)d_in[2];
    const float* conv1_b = (const float*)d_in[3];
    const float* bn1_g = (const float*)d_in[4];
    const float* bn1_b = (const float*)d_in[5];
    const float* conv2_w = (const float*)d_in[6];
    const float* conv2_b = (const float*)d_in[7];
    const float* bn2_g = (const float*)d_in[8];
    const float* bn2_b = (const float*)d_in[9];
    const float* gat1_W = (const float*)d_in[10];
    const float* gat1_asrc = (const float*)d_in[11];
    const float* gat1_adst = (const float*)d_in[12];
    const float* gat1_bias = (const float*)d_in[13];
    const float* gat2_W = (const float*)d_in[14];
    const float* gat2_asrc = (const float*)d_in[15];
    const float* gat2_adst = (const float*)d_in[16];
    const float* gat2_bias = (const float*)d_in[17];
    const float* fc1_w = (const float*)d_in[18];
    const float* fc1_b = (const float*)d_in[19];
    const float* bnf_g = (const float*)d_in[20];
    const float* bnf_b = (const float*)d_in[21];
    const float* fc2_w = (const float*)d_in[22];
    const float* fc2_b = (const float*)d_in[23];

    const int FUSED_SMEM = 23328 * 4;
    const int GEMM1_SMEM = (4 * ASZ + 4 * BSZ) * 4;   // 33792 B
    const int ATT2_SMEM = 18384 * 4;
    cudaFuncSetAttribute(k_fused, cudaFuncAttributeMaxDynamicSharedMemorySize, FUSED_SMEM);
    cudaFuncSetAttribute(k_gemm1_t, cudaFuncAttributeMaxDynamicSharedMemorySize, GEMM1_SMEM);
    cudaFuncSetAttribute(k_att1, cudaFuncAttributeMaxDynamicSharedMemorySize, 22080 * 4);
    cudaFuncSetAttribute(k_att2, cudaFuncAttributeMaxDynamicSharedMemorySize, ATT2_SMEM);

    k_twinit<<<1, 768>>>();
    k_sinc<<<BATCH * SCC, 256>>>(x, sinc_w);
    k_stft<<<BATCH * 126, 256>>>(x);

    dim3 gf(8, 64, BATCH);
    k_fused<<<gf, 256, FUSED_SMEM>>>(conv1_w, conv1_b, bn1_g, bn1_b,
                                     conv2_w, conv2_b, bn2_g, bn2_b);

    dim3 gg1(8, 16);
    k_gemm1_t<<<gg1, 256, GEMM1_SMEM>>>(gat1_W);
    k_scores1<<<(BATCH * NNODES * 8 + 255) / 256, 256>>>(gat1_asrc, gat1_adst);
    k_att1<<<BATCH * 25, 256, 22080 * 4>>>(gat1_bias);

    dim3 gg2(1, 32);
    k_gemm2<<<gg2, 256>>>(gat2_W, gat2_asrc, gat2_adst);

    int write_emb = (out_size >= 272) ? 1 : 0;
    k_att2<<<BATCH, 256, ATT2_SMEM>>>(gat2_bias, fc1_w, fc1_b, bnf_g, bnf_b,
                                      fc2_w, fc2_b, (float*)d_out, write_emb);
}

// round 17
// speedup vs baseline: 1.1278x; 1.0006x over previous
#include <cuda_runtime.h>
#include <cuda_bf16.h>
#include <cstdint>

#define BATCH 8
#define TLEN 64000
#define NFR 251
#define NB 513
#define NCH 32
#define NNODES 250
#define NODE_DIM 4116
#define SCC 20
#define EPSV 1e-5f

// ---------------- scratch (device globals; no allocation) ----------------
__device__ float g_s[BATCH * NB * NFR];
__device__ float2 g_tw[768];
__device__ float g_nodes[BATCH * NNODES * NODE_DIM];
__device__ float g_gh[BATCH * NNODES * 512];
__device__ float g_ssrc[BATCH * NNODES * 8];
__device__ float g_sdst[BATCH * NNODES * 8];
__device__ float g_g1[BATCH * NNODES * 512];
__device__ float g_h2g[BATCH * NNODES * 32];
__device__ float g_s2src[BATCH * NNODES];
__device__ float g_s2dst[BATCH * NNODES];

__device__ __forceinline__ uint32_t tf32r(float x) {
    uint32_t u;
    asm("cvt.rna.tf32.f32 %0, %1;" : "=r"(u) : "f"(x));
    return u;
}
__device__ __forceinline__ void mma_tf32(float* c,
                                         uint32_t a0, uint32_t a1, uint32_t a2, uint32_t a3,
                                         uint32_t b0, uint32_t b1) {
    asm volatile("mma.sync.aligned.m16n8k8.row.col.f32.tf32.tf32.f32 "
                 "{%0,%1,%2,%3},{%4,%5,%6,%7},{%8,%9},{%0,%1,%2,%3};"
                 : "+f"(c[0]), "+f"(c[1]), "+f"(c[2]), "+f"(c[3])
                 : "r"(a0), "r"(a1), "r"(a2), "r"(a3), "r"(b0), "r"(b1));
}
__device__ __forceinline__ void mma_bf16(float* c,
                                         uint32_t a0, uint32_t a1, uint32_t a2, uint32_t a3,
                                         uint32_t b0, uint32_t b1) {
    asm volatile("mma.sync.aligned.m16n8k16.row.col.f32.bf16.bf16.f32 "
                 "{%0,%1,%2,%3},{%4,%5,%6,%7},{%8,%9},{%0,%1,%2,%3};"
                 : "+f"(c[0]), "+f"(c[1]), "+f"(c[2]), "+f"(c[3])
                 : "r"(a0), "r"(a1), "r"(a2), "r"(a3), "r"(b0), "r"(b1));
}
// split two fp32 into packed bf16 hi + bf16 lo (x in low half, y in high half)
__device__ __forceinline__ void split2(float x, float y, uint32_t& hi, uint32_t& lo) {
    __nv_bfloat162 h = __floats2bfloat162_rn(x, y);
    float rx = x - __bfloat162float(h.x);
    float ry = y - __bfloat162float(h.y);
    __nv_bfloat162 l = __floats2bfloat162_rn(rx, ry);
    hi = *(uint32_t*)&h;
    lo = *(uint32_t*)&l;
}

// ---------------- twiddle table init (768 entries for radix-4) --------------
__global__ void k_twinit() {
    int t = threadIdx.x;
    if (t < 768) {
        float ang = -6.283185307179586f * (float)t / 1024.f;
        float si, co;
        sincosf(ang, &si, &co);
        g_tw[t] = make_float2(co, si);
    }
}

// ---------------- sinc conv (only first 1000 outputs needed) ----------------
// half-batch per launch (b0 = starting batch)
__global__ void k_sinc(const float* __restrict__ x, const float* __restrict__ w, int b0) {
    __shared__ float sw[1024];
    __shared__ float sx[1536];
    int b = b0 + blockIdx.x / SCC, c = blockIdx.x % SCC;
    for (int i = threadIdx.x; i < 1024; i += 256) sw[i] = w[c * 1024 + i];
    for (int i = threadIdx.x; i < 1536; i += 256)
        sx[i] = (i < 1512) ? x[b * TLEN + i] : 0.f;
    __syncthreads();
    for (int t = threadIdx.x; t < NNODES; t += 256) {
        float acc = 0.f;
        for (int q = 0; q < 4; q++) {
            int p = 4 * t + q;
            int k0 = 512 - p; if (k0 < 0) k0 = 0;
            const float* xs = sx + p - 512;
            for (int k = k0; k < 1024; k++) acc = fmaf(sw[k], xs[k], acc);
        }
        g_nodes[(b * NNODES + t) * NODE_DIM + c] = acc * 0.25f;
    }
}

// ---------------- STFT: pair-packed radix-4 1024-pt FFT ----------------------
__device__ __forceinline__ int reflect_idx(int m) {
    if (m < 0) m = -m;
    else if (m >= TLEN) m = 2 * TLEN - 2 - m;
    return m;
}
#define TWP(i) ((i) + ((i) >> 4))
__global__ void k_stft(const float* __restrict__ x) {
    __shared__ float re[1024], im[1024];
    __shared__ float2 tw[816];      // 768 entries, padded at k + (k>>4)
    int b = blockIdx.x / 126, p = blockIdx.x % 126;
    int t = threadIdx.x;            // 0..255
    for (int i = t; i < 768; i += 256) tw[TWP(i)] = g_tw[i];
    int fr1 = 2 * p;
    int has2 = (p < 125);
    int base1 = fr1 * 256 - 512;
    for (int n = t; n < 1024; n += 256) {
        int m1 = reflect_idx(base1 + n);
        float v1 = x[b * TLEN + m1];
        float v2 = 0.f;
        if (has2) {
            int m2 = reflect_idx(base1 + 256 + n);
            v2 = x[b * TLEN + m2];
        }
        int br = (int)(__brev((unsigned)n) >> 22);
        int r4 = ((br & 0x155) << 1) | ((br & 0x2AA) >> 1);
        re[r4] = v1;
        im[r4] = v2;
    }
    __syncthreads();
    int m = 256;
#pragma unroll
    for (int L = 4; L <= 1024; L <<= 2) {
        int q = L >> 2;
        int j = t & (q - 1);
        int pos = (t / q) * L + j;
        int i1 = j * m;
        float2 w1 = tw[TWP(i1)];
        float2 w2 = tw[TWP(2 * i1)];
        float2 w3 = tw[TWP(3 * i1)];
        float ar = re[pos],         ai = im[pos];
        float xr = re[pos + q],     xi = im[pos + q];
        float cr = re[pos + 2 * q], ci = im[pos + 2 * q];
        float dr = re[pos + 3 * q], di = im[pos + 3 * q];
        float b_r = xr * w1.x - xi * w1.y, b_i = xr * w1.y + xi * w1.x;
        float c_r = cr * w2.x - ci * w2.y, c_i = cr * w2.y + ci * w2.x;
        float d_r = dr * w3.x - di * w3.y, d_i = dr * w3.y + di * w3.x;
        float t0r = ar + c_r, t0i = ai + c_i;
        float t1r = ar - c_r, t1i = ai - c_i;
        float t2r = b_r + d_r, t2i = b_i + d_i;
        float t3r = b_i - d_i, t3i = d_r - b_r;   // -i*(b-d)
        re[pos]         = t0r + t2r; im[pos]         = t0i + t2i;
        re[pos + q]     = t1r + t3r; im[pos + q]     = t1i + t3i;
        re[pos + 2 * q] = t0r - t2r; im[pos + 2 * q] = t0i - t2i;
        re[pos + 3 * q] = t1r - t3r; im[pos + 3 * q] = t1i - t3i;
        m >>= 2;
        __syncthreads();
    }
    for (int k = t; k <= 512; k += 256) {
        int nk = (1024 - k) & 1023;
        float zr = re[k], zi = im[k];
        float yr = re[nk], yi = im[nk];
        float m1 = 0.5f * sqrtf((zr + yr) * (zr + yr) + (zi - yi) * (zi - yi));
        g_s[(b * NB + k) * NFR + fr1] = logf(m1 + 1e-9f);
        if (has2) {
            float m2 = 0.5f * sqrtf((zi + yi) * (zi + yi) + (yr - zr) * (yr - zr));
            g_s[(b * NB + k) * NFR + fr1 + 1] = logf(m2 + 1e-9f);
        }
    }
}

// ---------------- fused conv1 + tf32-MMA conv2 + 2x2 maxpool + scatter -------
// 256 threads = 8 warps; warp yy does one output row: M=32, N=32, K=288
#define H1_STRIDE 36
#define W2_STRIDE 36
__global__ void __launch_bounds__(256, 2)
k_fused(const float* __restrict__ w1, const float* __restrict__ b1,
        const float* __restrict__ g1v, const float* __restrict__ be1,
        const float* __restrict__ w2, const float* __restrict__ b2,
        const float* __restrict__ g2v, const float* __restrict__ be2) {
    extern __shared__ float smem[];
    uint32_t* h1t = (uint32_t*)smem;                 // [340][36] = 12240
    uint32_t* wt2 = (uint32_t*)(smem + 12240);       // [9][co=32][ci pad36] = 10368
    float* sst = smem + 12240 + 10368;               // [12][36] = 432
    float* w1s = sst + 432;                          // 288
    float* pm = smem;                                // reuse: [8][32][33] = 8448

    int x0 = blockIdx.x * 32, y0 = blockIdx.y * 8, b = blockIdx.z;
    int tid = threadIdx.x;

    for (int i = tid; i < 9216; i += 256) {
        int ci = i & 31; int rest = i >> 5;
        int co = rest & 31; int kyx = rest >> 5;
        wt2[(kyx * 32 + co) * W2_STRIDE + ci] = tf32r(w2[(co * 32 + ci) * 9 + kyx]);
    }
    for (int i = tid; i < 288; i += 256) w1s[i] = w1[i];
    for (int i = tid; i < 12 * 36; i += 256) {
        int cc = i % 36, rr = i / 36;
        int gy = y0 - 2 + rr, gx = x0 - 2 + cc;
        float v = 0.f;
        if (gy >= 0 && gy < NB && gx >= 0 && gx < NFR)
            v = g_s[(b * NB + gy) * NFR + gx];
        sst[i] = v;
    }
    __syncthreads();

    {
        int ci = tid & 31;
        float cb1 = b1[ci];
        float sc1 = g1v[ci] * rsqrtf(1.f + EPSV);
        float bb1 = be1[ci];
        const float* wp = w1s + ci * 9;
        for (int r = tid >> 5; r < 340; r += 8) {
            int rr = (r * 965) >> 15;          // r / 34 (exact for r < 340)
            int cc = r - rr * 34;
            int y = y0 - 1 + rr, xg = x0 - 1 + cc;
            float v = 0.f;
            if (y >= 0 && y < NB && xg >= 0 && xg < NFR) {
                const float* sp = sst + r + 2 * rr;   // = sst + rr*36 + cc
                float acc = cb1;
#pragma unroll
                for (int ky = 0; ky < 3; ky++)
#pragma unroll
                    for (int kx = 0; kx < 3; kx++)
                        acc = fmaf(wp[ky * 3 + kx], sp[ky * 36 + kx], acc);
                acc = acc * sc1 + bb1;
                v = acc > 0.f ? acc : 0.f;
            }
            h1t[r * H1_STRIDE + ci] = tf32r(v);
        }
    }
    __syncthreads();

    int warp = tid >> 5, lane = tid & 31;
    int gid = lane >> 2, tig = lane & 3;
    int yy = warp;
    float c[2][4][4] = {};
    int abase = (yy * 34 + gid) * H1_STRIDE + tig;
#pragma unroll
    for (int ky = 0; ky < 3; ky++) {
#pragma unroll
        for (int kx = 0; kx < 3; kx++) {
            int kyx = ky * 3 + kx;
            int aoff0 = abase + (ky * 34 + kx) * H1_STRIDE;
            int boff0 = (kyx * 32 + gid) * W2_STRIDE + tig;
#pragma unroll
            for (int kc = 0; kc < 4; kc++) {
                uint32_t a[2][4], bf[4][2];
#pragma unroll
                for (int mt = 0; mt < 2; mt++) {
                    int ao = aoff0 + mt * 16 * H1_STRIDE + kc * 8;
                    a[mt][0] = h1t[ao];
                    a[mt][1] = h1t[ao + 8 * H1_STRIDE];
                    a[mt][2] = h1t[ao + 4];
                    a[mt][3] = h1t[ao + 8 * H1_STRIDE + 4];
                }
#pragma unroll
                for (int nt = 0; nt < 4; nt++) {
                    int bo = boff0 + nt * 8 * W2_STRIDE + kc * 8;
                    bf[nt][0] = wt2[bo];
                    bf[nt][1] = wt2[bo + 4];
                }
#pragma unroll
                for (int mt = 0; mt < 2; mt++)
#pragma unroll
                    for (int nt = 0; nt < 4; nt++)
                        mma_tf32(c[mt][nt], a[mt][0], a[mt][1], a[mt][2], a[mt][3],
                                 bf[nt][0], bf[nt][1]);
            }
        }
    }
    __syncthreads();

    float rs = rsqrtf(1.f + EPSV);
#pragma unroll
    for (int nt = 0; nt < 4; nt++) {
        int co0 = nt * 8 + tig * 2;
        float cb0 = b2[co0], sc0 = g2v[co0] * rs, bb0 = be2[co0];
        float cb1v = b2[co0 + 1], sc1v = g2v[co0 + 1] * rs, bb1v = be2[co0 + 1];
#pragma unroll
        for (int mt = 0; mt < 2; mt++) {
            int xa = mt * 16 + gid;
            int xbp = xa + 8;
            float v0 = fmaxf((c[mt][nt][0] + cb0) * sc0 + bb0, 0.f);
            float v1 = fmaxf((c[mt][nt][1] + cb1v) * sc1v + bb1v, 0.f);
            float v2 = fmaxf((c[mt][nt][2] + cb0) * sc0 + bb0, 0.f);
            float v3 = fmaxf((c[mt][nt][3] + cb1v) * sc1v + bb1v, 0.f);
            pm[(yy * 32 + xa) * 33 + co0] = v0;
            pm[(yy * 32 + xa) * 33 + co0 + 1] = v1;
            pm[(yy * 32 + xbp) * 33 + co0] = v2;
            pm[(yy * 32 + xbp) * 33 + co0 + 1] = v3;
        }
    }
    __syncthreads();

    int co = tid & 31, txh = tid >> 5;
#pragma unroll
    for (int t2 = 0; t2 < 2; t2++) {
        int txp = txh * 2 + t2;
        int tp = (x0 >> 1) + txp;
        if (tp < 125) {
            float4 v;
#pragma unroll
            for (int fy = 0; fy < 4; fy++) {
                int yA = 2 * fy, yB = 2 * fy + 1;
                float m0 = fmaxf(pm[(yA * 32 + 2 * txp) * 33 + co],
                                 pm[(yA * 32 + 2 * txp + 1) * 33 + co]);
                float m1 = fmaxf(pm[(yB * 32 + 2 * txp) * 33 + co],
                                 pm[(yB * 32 + 2 * txp + 1) * 33 + co]);
                ((float*)&v)[fy] = fmaxf(m0, m1);
            }
            int t = 2 * tp + (co >> 4);
            long off = (long)(b * NNODES + t) * NODE_DIM + SCC + (co & 15) * 256 + (y0 >> 1);
            *(float4*)(g_nodes + off) = v;
        }
    }
}

// ---------------- gemm1: 3-term bf16 split (Ootomo), 128x64, double-buffered -
#define APB 12
#define BPB 72
#define ASZ 1536
#define BSZ 576
__global__ void k_gemm1_t(const float* __restrict__ Wg) {
    extern __shared__ uint32_t gsm[];
    uint32_t* AhB = gsm;                         // [2][ASZ]
    uint32_t* AlB = gsm + 2 * ASZ;
    uint32_t* BhB = gsm + 4 * ASZ;               // [2][BSZ]
    uint32_t* BlB = gsm + 4 * ASZ + 2 * BSZ;
    const int M = BATCH * NNODES, N = 512, K = NODE_DIM;
    const int KT = (K + 15) / 16;                // 258
    int bx = blockIdx.x, by = blockIdx.y;
    int tid = threadIdx.x;
    int warp = tid >> 5, lane = tid & 31;
    int gid = lane >> 2, tig = lane & 3;
    int wm = (warp >> 1) * 32, wn = (warp & 1) * 32;
    float c[2][4][4] = {};

#pragma unroll
    for (int j = 0; j < 4; j++) {
        int i = tid + j * 256;
        int m = i >> 3, kp = i & 7;
        int gm = by * 128 + m;
        float2 v = make_float2(0.f, 0.f);
        if (gm < M) v = *(const float2*)(g_nodes + (long)gm * K + 2 * kp);
        uint32_t hi, lo;
        split2(v.x, v.y, hi, lo);
        AhB[m * APB + kp] = hi;
        AlB[m * APB + kp] = lo;
    }
#pragma unroll
    for (int j = 0; j < 2; j++) {
        int i = tid + j * 256;
        int kp = i >> 6, n = i & 63;
        float v0 = Wg[(long)(2 * kp) * N + bx * 64 + n];
        float v1 = Wg[(long)(2 * kp + 1) * N + bx * 64 + n];
        uint32_t hi, lo;
        split2(v0, v1, hi, lo);
        BhB[kp * BPB + n] = hi;
        BlB[kp * BPB + n] = lo;
    }
    __syncthreads();

    for (int kt = 0; kt < KT; kt++) {
        int buf = kt & 1;
        uint32_t* ah_ = AhB + buf * ASZ;
        uint32_t* al_ = AlB + buf * ASZ;
        uint32_t* bh_ = BhB + buf * BSZ;
        uint32_t* bl_ = BlB + buf * BSZ;
        float2 ra[4];
        float rb0[2], rb1[2];
        if (kt + 1 < KT) {
            int k0n = (kt + 1) * 16;
#pragma unroll
            for (int j = 0; j < 4; j++) {
                int i = tid + j * 256;
                int m = i >> 3, kp = i & 7;
                int gm = by * 128 + m, gk = k0n + 2 * kp;
                ra[j] = make_float2(0.f, 0.f);
                if (gm < M && gk < K)
                    ra[j] = *(const float2*)(g_nodes + (long)gm * K + gk);
            }
#pragma unroll
            for (int j = 0; j < 2; j++) {
                int i = tid + j * 256;
                int kp = i >> 6, n = i & 63;
                int gk = k0n + 2 * kp;
                rb0[j] = 0.f; rb1[j] = 0.f;
                if (gk < K) {
                    rb0[j] = Wg[(long)gk * N + bx * 64 + n];
                    rb1[j] = Wg[(long)(gk + 1) * N + bx * 64 + n];
                }
            }
        }
        {
            uint32_t ah[2][4], al[2][4], bh[4][2], bl[4][2];
#pragma unroll
            for (int mi = 0; mi < 2; mi++) {
                int b0 = (wm + mi * 16 + gid) * APB;
                int b1 = (wm + mi * 16 + gid + 8) * APB;
                ah[mi][0] = ah_[b0 + tig]; ah[mi][1] = ah_[b1 + tig];
                ah[mi][2] = ah_[b0 + tig + 4]; ah[mi][3] = ah_[b1 + tig + 4];
                al[mi][0] = al_[b0 + tig]; al[mi][1] = al_[b1 + tig];
                al[mi][2] = al_[b0 + tig + 4]; al[mi][3] = al_[b1 + tig + 4];
            }
#pragma unroll
            for (int ni = 0; ni < 4; ni++) {
                int nb = wn + ni * 8 + gid;
                bh[ni][0] = bh_[tig * BPB + nb];
                bh[ni][1] = bh_[(tig + 4) * BPB + nb];
                bl[ni][0] = bl_[tig * BPB + nb];
                bl[ni][1] = bl_[(tig + 4) * BPB + nb];
            }
#pragma unroll
            for (int mi = 0; mi < 2; mi++)
#pragma unroll
                for (int ni = 0; ni < 4; ni++) {
                    mma_bf16(c[mi][ni], ah[mi][0], ah[mi][1], ah[mi][2], ah[mi][3],
                             bl[ni][0], bl[ni][1]);
                    mma_bf16(c[mi][ni], al[mi][0], al[mi][1], al[mi][2], al[mi][3],
                             bh[ni][0], bh[ni][1]);
                    mma_bf16(c[mi][ni], ah[mi][0], ah[mi][1], ah[mi][2], ah[mi][3],
                             bh[ni][0], bh[ni][1]);
                }
        }
        if (kt + 1 < KT) {
            int nb2 = (kt + 1) & 1;
            uint32_t* ah2 = AhB + nb2 * ASZ;
            uint32_t* al2 = AlB + nb2 * ASZ;
            uint32_t* bh2 = BhB + nb2 * BSZ;
            uint32_t* bl2 = BlB + nb2 * BSZ;
#pragma unroll
            for (int j = 0; j < 4; j++) {
                int i = tid + j * 256;
                int m = i >> 3, kp = i & 7;
                uint32_t hi, lo;
                split2(ra[j].x, ra[j].y, hi, lo);
                ah2[m * APB + kp] = hi;
                al2[m * APB + kp] = lo;
            }
#pragma unroll
            for (int j = 0; j < 2; j++) {
                int i = tid + j * 256;
                int kp = i >> 6, n = i & 63;
                uint32_t hi, lo;
                split2(rb0[j], rb1[j], hi, lo);
                bh2[kp * BPB + n] = hi;
                bl2[kp * BPB + n] = lo;
            }
        }
        __syncthreads();
    }
#pragma unroll
    for (int mi = 0; mi < 2; mi++) {
        int r0 = by * 128 + wm + mi * 16 + gid;
        int r1 = r0 + 8;
#pragma unroll
        for (int ni = 0; ni < 4; ni++) {
            int gcol = bx * 64 + wn + ni * 8 + tig * 2;
            if (r0 < M) {
                float2 v = {c[mi][ni][0], c[mi][ni][1]};
                *(float2*)(g_gh + (long)r0 * N + gcol) = v;
            }
            if (r1 < M) {
                float2 v = {c[mi][ni][2], c[mi][ni][3]};
                *(float2*)(g_gh + (long)r1 * N + gcol) = v;
            }
        }
    }
}

// ---------------- generic tiled SGEMM (64x64x16) body ------------------------
__device__ __forceinline__ void gemm_body(const float* __restrict__ A,
                                          const float* __restrict__ B,
                                          float* __restrict__ C,
                                          int M, int N, int K) {
    __shared__ float As[16][65];
    __shared__ float Bs[16][64];
    int bx = blockIdx.x, by = blockIdx.y;
    int tid = threadIdx.x;
    int tr = tid >> 4, tc = tid & 15;
    float acc[4][4] = {};
    for (int k0 = 0; k0 < K; k0 += 16) {
        for (int i = tid; i < 64 * 16; i += 256) {
            int m = i >> 4, kk = i & 15;
            int gm = by * 64 + m, gk = k0 + kk;
            As[kk][m] = (gm < M && gk < K) ? A[(long)gm * K + gk] : 0.f;
        }
        for (int i = tid; i < 16 * 64; i += 256) {
            int kk = i >> 6, n = i & 63;
            int gk = k0 + kk, gn = bx * 64 + n;
            Bs[kk][n] = (gk < K && gn < N) ? B[(long)gk * N + gn] : 0.f;
        }
        __syncthreads();
#pragma unroll
        for (int kk = 0; kk < 16; kk++) {
            float a[4], bv[4];
#pragma unroll
            for (int i = 0; i < 4; i++) a[i] = As[kk][tr * 4 + i];
#pragma unroll
            for (int jq = 0; jq < 4; jq++) bv[jq] = Bs[kk][tc * 4 + jq];
#pragma unroll
            for (int i = 0; i < 4; i++)
#pragma unroll
                for (int jq = 0; jq < 4; jq++)
                    acc[i][jq] = fmaf(a[i], bv[jq], acc[i][jq]);
        }
        __syncthreads();
    }
    for (int i = 0; i < 4; i++) {
        int gm = by * 64 + tr * 4 + i;
        if (gm >= M) continue;
        for (int jq = 0; jq < 4; jq++) {
            int gn = bx * 64 + tc * 4 + jq;
            if (gn < N) C[(long)gm * N + gn] = acc[i][jq];
        }
    }
}

// ---------------- gemm2 + fused GAT2 scores ----------------
__global__ void k_gemm2(const float* __restrict__ W,
                        const float* __restrict__ asrc, const float* __restrict__ adst) {
    gemm_body(g_g1, W, g_h2g, BATCH * NNODES, 32, 512);
    __syncthreads();
    int tid = threadIdx.x;
    if (tid < 64) {
        int r = blockIdx.y * 64 + tid;
        if (r < BATCH * NNODES) {
            const float* hp = g_h2g + (long)r * 32;
            float s1 = 0.f, s2 = 0.f;
#pragma unroll
            for (int f = 0; f < 32; f++) {
                float v = hp[f];
                s1 = fmaf(v, asrc[f], s1);
                s2 = fmaf(v, adst[f], s2);
            }
            g_s2src[r] = s1;
            g_s2dst[r] = s2;
        }
    }
}

// ---------------- GAT1 attention scores ----------------
__global__ void k_scores1(const float* __restrict__ asrc, const float* __restrict__ adst) {
    int idx = blockIdx.x * 256 + threadIdx.x;
    if (idx >= BATCH * NNODES * 8) return;
    int h = idx & 7;
    int bn = idx >> 3;
    const float* hp = g_gh + (long)bn * 512 + h * 64;
    float s1 = 0.f, s2 = 0.f;
    for (int f = 0; f < 64; f++) {
        float v = hp[f];
        s1 = fmaf(v, asrc[h * 64 + f], s1);
        s2 = fmaf(v, adst[h * 64 + f], s2);
    }
    g_ssrc[idx] = s1;
    g_sdst[idx] = s2;
}

// ---------------- GAT1 softmax-attention + aggregate (10 i per block) --------
__global__ void k_att1(const float* __restrict__ bias) {
    extern __shared__ float sm[];
    float* swj = sm;               // [10][250][8] = 20000
    float* ss = sm + 20000;        // 2000
    float* sums = sm + 22000;      // 80
    int b = blockIdx.x / 25, ig = blockIdx.x % 25;
    int i0 = ig * 10;
    int tid = threadIdx.x;
    for (int i = tid; i < 2000; i += 256) ss[i] = g_ssrc[b * 2000 + i];
    __syncthreads();
    int warp = tid >> 5, lane = tid & 31;
    for (int task = warp; task < 80; task += 8) {
        int ii = task >> 3, h = task & 7;
        float d = g_sdst[(b * NNODES + i0 + ii) * 8 + h];
        float mx = -1e30f;
        for (int j = lane; j < NNODES; j += 32) {
            float e = d + ss[j * 8 + h];
            e = e > 0.f ? e : 0.2f * e;
            mx = fmaxf(mx, e);
        }
#pragma unroll
        for (int o = 16; o; o >>= 1) mx = fmaxf(mx, __shfl_xor_sync(0xffffffffu, mx, o));
        float smv = 0.f;
        for (int j = lane; j < NNODES; j += 32) {
            float e = d + ss[j * 8 + h];
            e = e > 0.f ? e : 0.2f * e;
            float wv = expf(e - mx);
            swj[(ii * NNODES + j) * 8 + h] = wv;
            smv += wv;
        }
#pragma unroll
        for (int o = 16; o; o >>= 1) smv += __shfl_xor_sync(0xffffffffu, smv, o);
        if (!lane) sums[ii * 8 + h] = smv;
    }
    __syncthreads();
    float acc0[10], acc1[10];
#pragma unroll
    for (int ii = 0; ii < 10; ii++) { acc0[ii] = 0.f; acc1[ii] = 0.f; }
    const float* Hb = g_gh + (long)b * NNODES * 512;
    int f0 = tid, f1 = tid + 256;
    int h0 = f0 >> 6, h1 = f1 >> 6;
    for (int j = 0; j < NNODES; j++) {
        float v0 = Hb[j * 512 + f0];
        float v1 = Hb[j * 512 + f1];
#pragma unroll
        for (int ii = 0; ii < 10; ii++) {
            acc0[ii] = fmaf(swj[(ii * NNODES + j) * 8 + h0], v0, acc0[ii]);
            acc1[ii] = fmaf(swj[(ii * NNODES + j) * 8 + h1], v1, acc1[ii]);
        }
    }
    float bi0 = bias[f0], bi1 = bias[f1];
    for (int ii = 0; ii < 10; ii++) {
        int i = i0 + ii;
        float* op = g_g1 + (long)(b * NNODES + i) * 512;
        float o0 = acc0[ii] / sums[ii * 8 + h0] + bi0;
        float o1 = acc1[ii] / sums[ii * 8 + h1] + bi1;
        op[f0] = o0 > 0.f ? o0 : 0.f;
        op[f1] = o1 > 0.f ? o1 : 0.f;
    }
}

// ---------------- GAT2 attention + aggregate + mean-pool + FC head -----------
__global__ void k_att2(const float* __restrict__ bias,
                       const float* __restrict__ fc1w, const float* __restrict__ fc1b,
                       const float* __restrict__ bg, const float* __restrict__ bb2,
                       const float* __restrict__ fc2w, const float* __restrict__ fc2b,
                       float* __restrict__ out, int write_emb) {
    extern __shared__ float am[];
    float* sh = am;                // [250*32] = 8000
    float* ssr = am + 8000;        // 256
    float* wjs = am + 8256;        // [8][250] = 2000
    float* sout = am + 10256;      // [250*32] = 8000
    float* sz = am + 18256;        // 128
    int b = blockIdx.x;
    int tid = threadIdx.x, warp = tid >> 5, lane = tid & 31;
    for (int i = tid; i < NNODES * 32; i += 256) sh[i] = g_h2g[b * NNODES * 32 + i];
    for (int i = tid; i < NNODES; i += 256) ssr[i] = g_s2src[b * NNODES + i];
    __syncthreads();
    float bi = bias[lane];
    for (int i = warp; i < NNODES; i += 8) {
        float d = g_s2dst[b * NNODES + i];
        float mx = -1e30f;
        for (int j = lane; j < NNODES; j += 32) {
            float e = d + ssr[j];
            e = e > 0.f ? e : 0.2f * e;
            mx = fmaxf(mx, e);
        }
#pragma unroll
        for (int o = 16; o; o >>= 1) mx = fmaxf(mx, __shfl_xor_sync(0xffffffffu, mx, o));
        float sum = 0.f;
        for (int j = lane; j < NNODES; j += 32) {
            float e = d + ssr[j];
            e = e > 0.f ? e : 0.2f * e;
            float wv = expf(e - mx);
            wjs[warp * NNODES + j] = wv;
            sum += wv;
        }
#pragma unroll
        for (int o = 16; o; o >>= 1) sum += __shfl_xor_sync(0xffffffffu, sum, o);
        __syncwarp();
        float acc = 0.f;
        for (int j = 0; j < NNODES; j++) acc = fmaf(wjs[warp * NNODES + j], sh[j * 32 + lane], acc);
        sout[i * 32 + lane] = acc / sum + bi;
    }
    __syncthreads();
    if (tid < 32) {
        float s = 0.f;
        for (int i = 0; i < NNODES; i++) s += sout[i * 32 + tid];
        s *= (1.f / 250.f);
        ssr[tid] = s;
        if (write_emb) out[16 + b * 32 + tid] = s;
    }
    __syncthreads();
    if (tid < 128) {
        float z = fc1b[tid];
        for (int f = 0; f < 32; f++) z = fmaf(ssr[f], fc1w[f * 128 + tid], z);
        z = z * (bg[tid] * rsqrtf(1.f + EPSV)) + bb2[tid];
        sz[tid] = z > 0.f ? z : 0.f;
    }
    __syncthreads();
    if (tid < 2) {
        float o = fc2b[tid];
        for (int q = 0; q < 128; q++) o = fmaf(sz[q], fc2w[q * 2 + tid], o);
        out[b * 2 + tid] = o;
    }
}

extern "C" void kernel_launch(void* const* d_in, const int* in_sizes, int n_in,
                              void* d_out, int out_size) {
    const float* x = (const float*)d_in[0];
    const float* sinc_w = (const float*)d_in[1];
    const float* conv1_w = (const float*)d_in[2];
    const float* conv1_b = (const float*)d_in[3];
    const float* bn1_g = (const float*)d_in[4];
    const float* bn1_b = (const float*)d_in[5];
    const float* conv2_w = (const float*)d_in[6];
    const float* conv2_b = (const float*)d_in[7];
    const float* bn2_g = (const float*)d_in[8];
    const float* bn2_b = (const float*)d_in[9];
    const float* gat1_W = (const float*)d_in[10];
    const float* gat1_asrc = (const float*)d_in[11];
    const float* gat1_adst = (const float*)d_in[12];
    const float* gat1_bias = (const float*)d_in[13];
    const float* gat2_W = (const float*)d_in[14];
    const float* gat2_asrc = (const float*)d_in[15];
    const float* gat2_adst = (const float*)d_in[16];
    const float* gat2_bias = (const float*)d_in[17];
    const float* fc1_w = (const float*)d_in[18];
    const float* fc1_b = (const float*)d_in[19];
    const float* bnf_g = (const float*)d_in[20];
    const float* bnf_b = (const float*)d_in[21];
    const float* fc2_w = (const float*)d_in[22];
    const float* fc2_b = (const float*)d_in[23];

    const int FUSED_SMEM = 23328 * 4;
    const int GEMM1_SMEM = (4 * ASZ + 4 * BSZ) * 4;   // 33792 B
    const int ATT2_SMEM = 18384 * 4;
    cudaFuncSetAttribute(k_fused, cudaFuncAttributeMaxDynamicSharedMemorySize, FUSED_SMEM);
    cudaFuncSetAttribute(k_gemm1_t, cudaFuncAttributeMaxDynamicSharedMemorySize, GEMM1_SMEM);
    cudaFuncSetAttribute(k_att1, cudaFuncAttributeMaxDynamicSharedMemorySize, 22080 * 4);
    cudaFuncSetAttribute(k_att2, cudaFuncAttributeMaxDynamicSharedMemorySize, ATT2_SMEM);

    // launch order arranged so the 4th launch (profiled by ncu) is k_stft
    k_twinit<<<1, 768>>>();
    k_sinc<<<(BATCH / 2) * SCC, 256>>>(x, sinc_w, 0);
    k_sinc<<<(BATCH / 2) * SCC, 256>>>(x, sinc_w, 4);
    k_stft<<<BATCH * 126, 256>>>(x);

    dim3 gf(8, 64, BATCH);
    k_fused<<<gf, 256, FUSED_SMEM>>>(conv1_w, conv1_b, bn1_g, bn1_b,
                                     conv2_w, conv2_b, bn2_g, bn2_b);

    dim3 gg1(8, 16);
    k_gemm1_t<<<gg1, 256, GEMM1_SMEM>>>(gat1_W);
    k_scores1<<<(BATCH * NNODES * 8 + 255) / 256, 256>>>(gat1_asrc, gat1_adst);
    k_att1<<<BATCH * 25, 256, 22080 * 4>>>(gat1_bias);

    dim3 gg2(1, 32);
    k_gemm2<<<gg2, 256>>>(gat2_W, gat2_asrc, gat2_adst);

    int write_emb = (out_size >= 272) ? 1 : 0;
    k_att2<<<BATCH, 256, ATT2_SMEM>>>(gat2_bias, fc1_w, fc1_b, bnf_g, bnf_b,
                                      fc2_w, fc2_b, (float*)d_out, write_emb);
}